// round 4
// baseline (speedup 1.0000x reference)
#include <cuda_runtime.h>
#include <math.h>
#include <stdint.h>

#define Bb   4
#define Dd   64
#define Hh   4
#define DHd  16
#define Nn   2304
#define BHh  16   // B*heads

#define LOG2E      1.4426950408889634f
#define HALF_LOG2E 0.7213475204444817f

// ---------------- scratch (device globals) ----------------------------------
__device__ float d_qt[BHh * DHd * Nn];     // q transposed: [bh][k][n]
__device__ float d_qn[BHh * Nn];           // 0.25*log2e*||q||^2
__device__ float d_z[BHh * Nn * DHd];      // Z n-major: [bh][m][c]
__device__ float d_u[BHh * Nn * DHd];      // U = softmax(P) @ Z   [bh][n][c]
__device__ float d_g[BHh * Nn * Dd];       // g = U @ R^T / 4
__device__ float d_v[BHh * DHd * Nn];      // v[bh][k][vc]
__device__ float d_bound[1];

__device__ __forceinline__ float ex2(float a) {
    float r;
    asm("ex2.approx.ftz.f32 %0, %1;" : "=f"(r) : "f"(a));
    return r;
}
__device__ __forceinline__ void lds2(uint64_t& a, uint64_t& b, uint32_t addr) {
    asm volatile("ld.shared.v2.b64 {%0,%1}, [%2];" : "=l"(a), "=l"(b) : "r"(addr));
}
__device__ __forceinline__ uint64_t fma2(uint64_t a, uint64_t b, uint64_t c) {
    uint64_t d;
    asm("fma.rn.f32x2 %0, %1, %2, %3;" : "=l"(d) : "l"(a), "l"(b), "l"(c));
    return d;
}
__device__ __forceinline__ uint64_t sub2(uint64_t a, uint64_t b) {
    uint64_t d;
    asm("sub.rn.f32x2 %0, %1, %2;" : "=l"(d) : "l"(a), "l"(b));
    return d;
}
__device__ __forceinline__ uint64_t pack2(float lo, float hi) {
    uint64_t d;
    asm("mov.b64 %0, {%1,%2};" : "=l"(d) : "f"(lo), "f"(hi));
    return d;
}
__device__ __forceinline__ void unpack2(float& lo, float& hi, uint64_t v) {
    asm("mov.b64 {%0,%1}, %2;" : "=f"(lo), "=f"(hi) : "l"(v));
}
__device__ __forceinline__ uint32_t smem_u32(const void* p) {
    return (uint32_t)__cvta_generic_to_shared(p);
}

// ---------------- K0: q = Wq x + bq (transposed out), qn scaled -------------
__global__ void __launch_bounds__(128) k_q(const float* __restrict__ x,
                                           const float* __restrict__ Wq,
                                           const float* __restrict__ bq) {
    __shared__ float sW[Hh * DHd * Dd];
    int tid = threadIdx.x;
    for (int i = tid; i < Hh * DHd * Dd; i += 128) sW[i] = Wq[i];
    __syncthreads();

    int b = blockIdx.y;
    int n = blockIdx.x * 128 + tid;
    const float* xb = x + b * Dd * Nn;

    float xv[Dd];
#pragma unroll
    for (int d = 0; d < Dd; d++) xv[d] = xb[d * Nn + n];

    for (int h = 0; h < Hh; h++) {
        int bh = b * Hh + h;
        float qn = 0.f;
#pragma unroll
        for (int k = 0; k < DHd; k++) {
            float acc = bq[h * DHd + k];
            const float* w = sW + (h * DHd + k) * Dd;
#pragma unroll
            for (int d = 0; d < Dd; d++) acc += w[d] * xv[d];
            d_qt[((size_t)bh * DHd + k) * Nn + n] = acc;
            qn += acc * acc;
        }
        d_qn[(size_t)bh * Nn + n] = qn * (0.25f * LOG2E);
    }
}

// ---------------- K_z: Z_h = x_r @ R_h (n-major out) ------------------------
__global__ void __launch_bounds__(256) k_z(const float* __restrict__ x,
                                           const float* __restrict__ Wq) {
    __shared__ float sR[Hh * Dd * DHd];
    int tid = threadIdx.x;
    for (int i = tid; i < 4096; i += 256) sR[i] = Wq[i];
    __syncthreads();

    int b = blockIdx.y;
    int m = blockIdx.x * 256 + tid;
    const float* xr = x + (size_t)b * Dd * Nn + (size_t)m * Dd;

    float xv[Dd];
#pragma unroll
    for (int dc = 0; dc < 16; dc++) {
        float4 v = *(const float4*)(xr + dc * 4);
        xv[dc * 4 + 0] = v.x; xv[dc * 4 + 1] = v.y;
        xv[dc * 4 + 2] = v.z; xv[dc * 4 + 3] = v.w;
    }
    for (int h = 0; h < Hh; h++) {
        int bh = b * Hh + h;
        float acc[DHd];
#pragma unroll
        for (int c = 0; c < DHd; c++) acc[c] = 0.f;
#pragma unroll
        for (int d = 0; d < Dd; d++) {
            float xd = xv[d];
            const float4* rr = (const float4*)(sR + h * 1024 + d * 16);
#pragma unroll
            for (int cc = 0; cc < 4; cc++) {
                float4 rv = rr[cc];
                acc[cc * 4 + 0] += xd * rv.x;
                acc[cc * 4 + 1] += xd * rv.y;
                acc[cc * 4 + 2] += xd * rv.z;
                acc[cc * 4 + 3] += xd * rv.w;
            }
        }
        float* zo = d_z + ((size_t)(bh) * Nn + m) * DHd;
#pragma unroll
        for (int cc = 0; cc < 4; cc++)
            *(float4*)(zo + cc * 4) = make_float4(acc[cc*4], acc[cc*4+1], acc[cc*4+2], acc[cc*4+3]);
    }
}

// ---------------- K_bound ----------------------------------------------------
__global__ void k_bound(const float* __restrict__ Wq,
                        const float* __restrict__ Wv,
                        const float* __restrict__ Wo) {
    __shared__ float red[256];
    __shared__ float sq[Hh], sv[Hh];
    int tid = threadIdx.x;
    for (int h = 0; h < Hh; h++) {
        float a = 0.f;
        for (int i = tid; i < 1024; i += 256) { float w = Wq[h * 1024 + i]; a += w * w; }
        red[tid] = a; __syncthreads();
        for (int s = 128; s > 0; s >>= 1) { if (tid < s) red[tid] += red[tid + s]; __syncthreads(); }
        if (tid == 0) sq[h] = red[0];
        __syncthreads();
        a = 0.f;
        for (int i = tid; i < 1024; i += 256) { float w = Wv[h * 1024 + i]; a += w * w; }
        red[tid] = a; __syncthreads();
        for (int s = 128; s > 0; s >>= 1) { if (tid < s) red[tid] += red[tid + s]; __syncthreads(); }
        if (tid == 0) sv[h] = red[0];
        __syncthreads();
    }
    float a = 0.f;
    for (int i = tid; i < 4096; i += 256) { float w = Wo[i]; a += w * w; }
    red[tid] = a; __syncthreads();
    for (int s = 128; s > 0; s >>= 1) { if (tid < s) red[tid] += red[tid + s]; __syncthreads(); }
    if (tid == 0) {
        double z = 2304.0 / 2.718281828459045;
        double w = log(z) - log(log(z));
        for (int it = 0; it < 30; it++) {
            double ew = exp(w);
            w = w - (w * ew - z) / (ew * (w + 1.0));
        }
        float phi = (float)w;
        float term = sqrtf(sq[0] * sv[0] + sq[1] * sv[1] + sq[2] * sv[2] + sq[3] * sv[3]);
        d_bound[0] = sqrtf(2304.f / 64.f) * (4.f * phi + 1.f) * term * sqrtf(red[0]);
    }
}

// ---------------- K1: flash with packed f32x2 FMA ----------------------------
// p_nm = exp2(0.5*log2e*(q.k) - qnl_n - qnl_m) <= 1 (row term kept; no max)
__global__ void __launch_bounds__(256, 2) k_flash() {
    int bh = blockIdx.y;
    int n0 = blockIdx.x * 64;
    int tid = threadIdx.x;
    int tx = tid & 15, ty = tid >> 4;

    __shared__ float sQd[16][128];     // Q duplicated pairs, pre-scaled
    __shared__ float sKt[16][64];      // K tile k-major
    __shared__ float sZ[64 * 20];      // Z tile m-major, row-permuted, pitch 20
    __shared__ float sKn[64];

    const float* qtb = d_qt + (size_t)bh * DHd * Nn;
    const float* zb  = d_z  + (size_t)bh * Nn * DHd;
    const float* qnb = d_qn + (size_t)bh * Nn;

    // ---- build duplicated Q tile (fixed for whole block) ----
    {
        int kk = tid >> 4, nl = (tid & 15) * 4;
        float4 v = *(const float4*)(qtb + (size_t)kk * Nn + n0 + nl);
        float4 a = make_float4(v.x * HALF_LOG2E, v.x * HALF_LOG2E,
                               v.y * HALF_LOG2E, v.y * HALF_LOG2E);
        float4 b = make_float4(v.z * HALF_LOG2E, v.z * HALF_LOG2E,
                               v.w * HALF_LOG2E, v.w * HALF_LOG2E);
        *(float4*)(&sQd[kk][2 * nl + 0]) = a;
        *(float4*)(&sQd[kk][2 * nl + 4]) = b;
    }
    // negated row norms (packed duplicates)
    uint64_t nqnl2[4];
    {
        float4 v = *(const float4*)(qnb + n0 + ty * 4);
        nqnl2[0] = pack2(-v.x, -v.x); nqnl2[1] = pack2(-v.y, -v.y);
        nqnl2[2] = pack2(-v.z, -v.z); nqnl2[3] = pack2(-v.w, -v.w);
    }

    uint64_t O2[4][8];
    float li[4];
#pragma unroll
    for (int i = 0; i < 4; i++) {
        li[i] = 0.f;
#pragma unroll
        for (int c = 0; c < 8; c++) O2[i][c] = 0ull;
    }

    // smem byte addresses
    uint32_t aQd = smem_u32(&sQd[0][0]) + ty * 32;           // + kk*512 per step
    uint32_t aKt = smem_u32(&sKt[0][0]) + tx * 16;           // + kk*256
    uint32_t aKn = smem_u32(&sKn[0]) + tx * 16;
    uint32_t aZr = smem_u32(&sZ[0]) + tx * 80;               // + j*1280

    // loader offsets
    int lrow = tid >> 4, lcol = (tid & 15) * 4;              // K tile
    int zr   = tid >> 2, zcg  = tid & 3;                     // Z tile
    int zslot = ((zr & 3) << 4) | (zr >> 2);
    float* zdst = &sZ[zslot * 20 + zcg * 4];

    // prefetch tile 0
    float4 pK = *(const float4*)(qtb + (size_t)lrow * Nn + lcol);
    float4 pZ = *(const float4*)(zb + (size_t)zr * DHd + zcg * 4);
    float pN = (tid < 64) ? qnb[tid] : 0.f;

    for (int t = 0; t < 36; t++) {
        __syncthreads();
        *(float4*)(&sKt[lrow][lcol]) = pK;
        *(float4*)zdst = pZ;
        if (tid < 64) sKn[tid] = pN;
        if (t < 35) {
            int m0 = (t + 1) * 64;
            pK = *(const float4*)(qtb + (size_t)lrow * Nn + m0 + lcol);
            pZ = *(const float4*)(zb + (size_t)(m0 + zr) * DHd + zcg * 4);
            if (tid < 64) pN = qnb[m0 + tid];
        }
        __syncthreads();

        // init accumulators with -(qnl_i + kn_j)
        uint64_t kn2a, kn2b;
        lds2(kn2a, kn2b, aKn);
        uint64_t s2[4][2];
#pragma unroll
        for (int i = 0; i < 4; i++) {
            s2[i][0] = sub2(nqnl2[i], kn2a);
            s2[i][1] = sub2(nqnl2[i], kn2b);
        }

        // gemm1: += 0.5*log2e * q.k (packed over m-pairs)
#pragma unroll
        for (int kk = 0; kk < 16; kk++) {
            uint64_t q01, q23, q45, q67, ka, kb;
            lds2(q01, q23, aQd + kk * 512);
            lds2(q45, q67, aQd + kk * 512 + 16);
            lds2(ka, kb, aKt + kk * 256);
            s2[0][0] = fma2(q01, ka, s2[0][0]); s2[0][1] = fma2(q01, kb, s2[0][1]);
            s2[1][0] = fma2(q23, ka, s2[1][0]); s2[1][1] = fma2(q23, kb, s2[1][1]);
            s2[2][0] = fma2(q45, ka, s2[2][0]); s2[2][1] = fma2(q45, kb, s2[2][1]);
            s2[3][0] = fma2(q67, ka, s2[3][0]); s2[3][1] = fma2(q67, kb, s2[3][1]);
        }

        // exp2 + li
        float p[4][4];
#pragma unroll
        for (int i = 0; i < 4; i++) {
            float a0, a1, a2, a3;
            unpack2(a0, a1, s2[i][0]);
            unpack2(a2, a3, s2[i][1]);
            p[i][0] = ex2(a0); p[i][1] = ex2(a1);
            p[i][2] = ex2(a2); p[i][3] = ex2(a3);
            li[i] += (p[i][0] + p[i][1]) + (p[i][2] + p[i][3]);
        }

        // gemm2: O2[i][cp] += p[i][j] * Z[m_j][2cp..2cp+1]
#pragma unroll
        for (int j = 0; j < 4; j++) {
            uint32_t az = aZr + j * 1280;
            uint64_t ps0 = pack2(p[0][j], p[0][j]);
            uint64_t ps1 = pack2(p[1][j], p[1][j]);
            uint64_t ps2 = pack2(p[2][j], p[2][j]);
            uint64_t ps3 = pack2(p[3][j], p[3][j]);
            uint64_t z0, z1;
#pragma unroll
            for (int half = 0; half < 4; half++) {
                lds2(z0, z1, az + half * 16);
                int cp = half * 2;
                O2[0][cp]   = fma2(ps0, z0, O2[0][cp]);   O2[0][cp+1] = fma2(ps0, z1, O2[0][cp+1]);
                O2[1][cp]   = fma2(ps1, z0, O2[1][cp]);   O2[1][cp+1] = fma2(ps1, z1, O2[1][cp+1]);
                O2[2][cp]   = fma2(ps2, z0, O2[2][cp]);   O2[2][cp+1] = fma2(ps2, z1, O2[2][cp+1]);
                O2[3][cp]   = fma2(ps3, z0, O2[3][cp]);   O2[3][cp+1] = fma2(ps3, z1, O2[3][cp+1]);
            }
        }
    }

    // unpack and reduce across the 16 tx lanes
    float O[4][16];
#pragma unroll
    for (int i = 0; i < 4; i++)
#pragma unroll
        for (int cp = 0; cp < 8; cp++)
            unpack2(O[i][2 * cp], O[i][2 * cp + 1], O2[i][cp]);

#pragma unroll
    for (int off = 8; off >= 1; off >>= 1) {
#pragma unroll
        for (int i = 0; i < 4; i++) {
            li[i] += __shfl_xor_sync(0xffffffffu, li[i], off);
#pragma unroll
            for (int c = 0; c < 16; c++)
                O[i][c] += __shfl_xor_sync(0xffffffffu, O[i][c], off);
        }
    }
    if (tx == 0) {
#pragma unroll
        for (int i = 0; i < 4; i++) {
            float inv = 1.f / li[i];
            float* uo = d_u + ((size_t)bh * Nn + n0 + ty * 4 + i) * DHd;
#pragma unroll
            for (int cc = 0; cc < 4; cc++)
                *(float4*)(uo + cc * 4) = make_float4(O[i][cc*4] * inv, O[i][cc*4+1] * inv,
                                                      O[i][cc*4+2] * inv, O[i][cc*4+3] * inv);
        }
    }
}

// ---------------- K_g: g = U @ R^T / 4 --------------------------------------
__global__ void __launch_bounds__(256) k_g(const float* __restrict__ Wq) {
    int bh = blockIdx.y;
    int h = bh & 3;
    int n0 = blockIdx.x * 64;
    int tid = threadIdx.x, ty = tid >> 4, tx = tid & 15;

    __shared__ float sUt[16][64];
    __shared__ float sRt[16][64];
    {
        int n = tid & 63, cg = tid >> 6;
        float4 v = *(const float4*)(d_u + ((size_t)bh * Nn + n0 + n) * DHd + cg * 4);
        sUt[cg * 4 + 0][n] = v.x; sUt[cg * 4 + 1][n] = v.y;
        sUt[cg * 4 + 2][n] = v.z; sUt[cg * 4 + 3][n] = v.w;
        int dd = tid & 63;
        float4 r = *(const float4*)(Wq + h * 1024 + dd * 16 + cg * 4);
        sRt[cg * 4 + 0][dd] = r.x; sRt[cg * 4 + 1][dd] = r.y;
        sRt[cg * 4 + 2][dd] = r.z; sRt[cg * 4 + 3][dd] = r.w;
    }
    __syncthreads();

    float acc[4][4];
#pragma unroll
    for (int i = 0; i < 4; i++)
#pragma unroll
        for (int j = 0; j < 4; j++) acc[i][j] = 0.f;
#pragma unroll
    for (int c = 0; c < 16; c++) {
        float4 uv = *(const float4*)(&sUt[c][ty * 4]);
        float4 rv = *(const float4*)(&sRt[c][tx * 4]);
        float u[4] = {uv.x, uv.y, uv.z, uv.w};
        float r[4] = {rv.x, rv.y, rv.z, rv.w};
#pragma unroll
        for (int i = 0; i < 4; i++)
#pragma unroll
            for (int j = 0; j < 4; j++) acc[i][j] += u[i] * r[j];
    }
#pragma unroll
    for (int i = 0; i < 4; i++) {
        float4 w = make_float4(acc[i][0] * 0.25f, acc[i][1] * 0.25f,
                               acc[i][2] * 0.25f, acc[i][3] * 0.25f);
        *(float4*)(d_g + ((size_t)bh * Nn + n0 + ty * 4 + i) * 64 + tx * 4) = w;
    }
}

// ---------------- K_v: v[bh][k][vc] = Wv . f_img + bv -----------------------
__global__ void __launch_bounds__(256) k_v(const float* __restrict__ Wv,
                                           const float* __restrict__ bv) {
    int bh = blockIdx.y;
    int h = bh & 3;
    int vc = blockIdx.x * 256 + threadIdx.x;
    __shared__ float sw[DHd * Dd];
    for (int i = threadIdx.x; i < 1024; i += 256) sw[i] = Wv[h * 1024 + i];
    __syncthreads();
    int a = vc >> 6;
    int r = vc & 63;
    const float* gb = d_g + (size_t)bh * Nn * 64;
    float gv[64];
#pragma unroll
    for (int dd = 0; dd < 64; dd++) gv[dd] = gb[(36 * dd + a) * 64 + r];
#pragma unroll
    for (int k = 0; k < 16; k++) {
        float acc = bv[h * 16 + k];
        const float* w = sw + k * 64;
#pragma unroll
        for (int dd = 0; dd < 64; dd++) acc += w[dd] * gv[dd];
        d_v[((size_t)bh * 16 + k) * Nn + vc] = acc;
    }
}

// ---------------- K_out: cat gather + Wo gemm + residual --------------------
__global__ void __launch_bounds__(256) k_out(const float* __restrict__ Wo,
                                             const float* __restrict__ bo,
                                             const float* __restrict__ gamma,
                                             const float* __restrict__ x,
                                             float* __restrict__ out) {
    int b = blockIdx.y;
    int n0 = blockIdx.x * 64;
    int a = n0 >> 6;
    int tid = threadIdx.x, ty = tid >> 4, tx = tid & 15;
    __shared__ __align__(16) float sC[64][68];
    __shared__ float sW[64][64];
    for (int i = tid; i < 4096; i += 256) {
        int dd = i >> 6, j = i & 63;
        int h = j >> 4, kk = j & 15;
        int vidx = (36 * dd + a) * 16 + kk;
        int vr = vidx / Nn;
        int vcol = vidx - vr * Nn;
        sC[dd][j] = d_v[((size_t)(b * Hh + h) * 16 + vr) * Nn + vcol];
    }
    for (int i = tid; i < 4096; i += 256) sW[i >> 6][i & 63] = Wo[i];
    __syncthreads();
    float acc[4][4];
#pragma unroll
    for (int i = 0; i < 4; i++)
#pragma unroll
        for (int c = 0; c < 4; c++) acc[i][c] = 0.f;
#pragma unroll 4
    for (int dd = 0; dd < 64; dd++) {
        float wv[4];
#pragma unroll
        for (int i = 0; i < 4; i++) wv[i] = sW[ty + 16 * i][dd];
        float4 cv = *(const float4*)(&sC[dd][tx * 4]);
#pragma unroll
        for (int i = 0; i < 4; i++) {
            acc[i][0] += wv[i] * cv.x;
            acc[i][1] += wv[i] * cv.y;
            acc[i][2] += wv[i] * cv.z;
            acc[i][3] += wv[i] * cv.w;
        }
    }
    float scale = gamma[0] / d_bound[0];
#pragma unroll
    for (int i = 0; i < 4; i++) {
        int o = ty + 16 * i;
        float bb = bo[o];
        size_t base = ((size_t)b * 64 + o) * Nn + n0 + tx * 4;
        float4 xin = *(const float4*)(&x[base]);
        float4 r;
        r.x = scale * (acc[i][0] + bb) + xin.x;
        r.y = scale * (acc[i][1] + bb) + xin.y;
        r.z = scale * (acc[i][2] + bb) + xin.z;
        r.w = scale * (acc[i][3] + bb) + xin.w;
        *(float4*)(&out[base]) = r;
    }
}

// ---------------- launch -----------------------------------------------------
extern "C" void kernel_launch(void* const* d_in, const int* in_sizes, int n_in,
                              void* d_out, int out_size) {
    const float* x     = (const float*)d_in[0];
    const float* Wq    = (const float*)d_in[1];
    const float* bq    = (const float*)d_in[2];
    const float* Wv    = (const float*)d_in[3];
    const float* bv    = (const float*)d_in[4];
    const float* Wo    = (const float*)d_in[5];
    const float* bo    = (const float*)d_in[6];
    const float* gamma = (const float*)d_in[7];
    float* out = (float*)d_out;

    k_q    <<<dim3(Nn / 128, Bb), 128>>>(x, Wq, bq);
    k_z    <<<dim3(Nn / 256, Bb), 256>>>(x, Wq);
    k_bound<<<1, 256>>>(Wq, Wv, Wo);
    k_flash<<<dim3(Nn / 64, BHh), 256>>>();
    k_g    <<<dim3(Nn / 64, BHh), 256>>>(Wq);
    k_v    <<<dim3(Nn / 256, BHh), 256>>>(Wv, bv);
    k_out  <<<dim3(Nn / 64, Bb), 256>>>(Wo, bo, gamma, x, out);
}

// round 5
// speedup vs baseline: 2.3147x; 2.3147x over previous
#include <cuda_runtime.h>
#include <cuda_bf16.h>
#include <math.h>
#include <stdint.h>

#define Bb   4
#define Dd   64
#define Hh   4
#define DHd  16
#define Nn   2304
#define BHh  16   // B*heads

#define LOG2E 1.4426950408889634f
#define SC    0.8493218593f   // sqrt(0.5*log2e)

// ---------------- scratch (device globals) ----------------------------------
__device__ uint32_t d_qb[BHh * Nn * 8];          // q bf16x2: [bh][n][k/2], q pre-scaled by SC
__device__ float d_qn[BHh * Nn];                 // 0.25*log2e*||q||^2
__device__ __nv_bfloat16 d_zb[BHh * DHd * Nn];   // Z bf16: [bh][c][m]
__device__ float d_u[BHh * Nn * DHd];            // U = softmax(P) @ Z   [bh][n][c]
__device__ float d_g[BHh * Nn * Dd];             // g = U @ R^T / 4
__device__ float d_v[BHh * DHd * Nn];            // v[bh][k][vc]
__device__ float d_bound[1];

__device__ __forceinline__ float ex2(float a) {
    float r;
    asm("ex2.approx.ftz.f32 %0, %1;" : "=f"(r) : "f"(a));
    return r;
}
__device__ __forceinline__ uint32_t cvt2(float lo, float hi) {
    uint32_t r;
    asm("cvt.rn.bf16x2.f32 %0, %1, %2;" : "=r"(r) : "f"(hi), "f"(lo));
    return r;
}
__device__ __forceinline__ uint32_t smem_u32(const void* p) {
    return (uint32_t)__cvta_generic_to_shared(p);
}
__device__ __forceinline__ void ldsm4(uint32_t& r0, uint32_t& r1, uint32_t& r2, uint32_t& r3,
                                      uint32_t addr) {
    asm volatile("ldmatrix.sync.aligned.m8n8.x4.shared.b16 {%0,%1,%2,%3}, [%4];"
                 : "=r"(r0), "=r"(r1), "=r"(r2), "=r"(r3) : "r"(addr));
}
__device__ __forceinline__ void mma16816(float& d0, float& d1, float& d2, float& d3,
                                         uint32_t a0, uint32_t a1, uint32_t a2, uint32_t a3,
                                         uint32_t b0, uint32_t b1,
                                         float c0, float c1, float c2, float c3) {
    asm volatile("mma.sync.aligned.m16n8k16.row.col.f32.bf16.bf16.f32 "
                 "{%0,%1,%2,%3},{%4,%5,%6,%7},{%8,%9},{%10,%11,%12,%13};"
                 : "=f"(d0), "=f"(d1), "=f"(d2), "=f"(d3)
                 : "r"(a0), "r"(a1), "r"(a2), "r"(a3), "r"(b0), "r"(b1),
                   "f"(c0), "f"(c1), "f"(c2), "f"(c3));
}

// ---------------- K0: q = Wq x + bq -> bf16 (scaled), qn -------------------
__global__ void __launch_bounds__(128) k_q(const float* __restrict__ x,
                                           const float* __restrict__ Wq,
                                           const float* __restrict__ bq) {
    __shared__ float sW[DHd * Dd];
    int tid = threadIdx.x;
    int h = blockIdx.z;
    for (int i = tid; i < DHd * Dd; i += 128) sW[i] = Wq[h * 1024 + i];
    __syncthreads();

    int b = blockIdx.y;
    int n = blockIdx.x * 128 + tid;
    int bh = b * Hh + h;
    const float* xb = x + b * Dd * Nn;

    float xv[Dd];
#pragma unroll
    for (int d = 0; d < Dd; d++) xv[d] = xb[d * Nn + n];

    float qv[DHd];
    float qn = 0.f;
#pragma unroll
    for (int k = 0; k < DHd; k++) {
        float acc = bq[h * DHd + k];
        const float* w = sW + k * Dd;
#pragma unroll
        for (int d = 0; d < Dd; d++) acc += w[d] * xv[d];
        qv[k] = acc;
        qn += acc * acc;
    }
    uint32_t pk[8];
#pragma unroll
    for (int i = 0; i < 8; i++) pk[i] = cvt2(SC * qv[2 * i], SC * qv[2 * i + 1]);
    uint4* dst = (uint4*)(d_qb + ((size_t)bh * Nn + n) * 8);
    dst[0] = make_uint4(pk[0], pk[1], pk[2], pk[3]);
    dst[1] = make_uint4(pk[4], pk[5], pk[6], pk[7]);
    d_qn[(size_t)bh * Nn + n] = qn * (0.25f * LOG2E);
}

// ---------------- K_z: Z_h = x_r @ R_h -> bf16 [bh][c][m] -------------------
__global__ void __launch_bounds__(256) k_z(const float* __restrict__ x,
                                           const float* __restrict__ Wq) {
    __shared__ float sR[Dd * DHd];
    int tid = threadIdx.x;
    int h = blockIdx.z;
    for (int i = tid; i < 1024; i += 256) sR[i] = Wq[h * 1024 + i];
    __syncthreads();

    int b = blockIdx.y;
    int m = blockIdx.x * 256 + tid;
    int bh = b * Hh + h;
    const float* xr = x + (size_t)b * Dd * Nn + (size_t)m * Dd;

    float acc[DHd];
#pragma unroll
    for (int c = 0; c < DHd; c++) acc[c] = 0.f;
#pragma unroll
    for (int dc = 0; dc < 16; dc++) {
        float4 v = *(const float4*)(xr + dc * 4);
        float xd[4] = {v.x, v.y, v.z, v.w};
#pragma unroll
        for (int q = 0; q < 4; q++) {
            const float4* rr = (const float4*)(sR + (dc * 4 + q) * 16);
#pragma unroll
            for (int cc = 0; cc < 4; cc++) {
                float4 rv = rr[cc];
                acc[cc * 4 + 0] += xd[q] * rv.x;
                acc[cc * 4 + 1] += xd[q] * rv.y;
                acc[cc * 4 + 2] += xd[q] * rv.z;
                acc[cc * 4 + 3] += xd[q] * rv.w;
            }
        }
    }
#pragma unroll
    for (int c = 0; c < DHd; c++)
        d_zb[((size_t)bh * DHd + c) * Nn + m] = __float2bfloat16_rn(acc[c]);
}

// ---------------- K_bound ----------------------------------------------------
__global__ void k_bound(const float* __restrict__ Wq,
                        const float* __restrict__ Wv,
                        const float* __restrict__ Wo) {
    __shared__ float red[256];
    __shared__ float sq[Hh], sv[Hh];
    int tid = threadIdx.x;
    for (int h = 0; h < Hh; h++) {
        float a = 0.f;
        for (int i = tid; i < 1024; i += 256) { float w = Wq[h * 1024 + i]; a += w * w; }
        red[tid] = a; __syncthreads();
        for (int s = 128; s > 0; s >>= 1) { if (tid < s) red[tid] += red[tid + s]; __syncthreads(); }
        if (tid == 0) sq[h] = red[0];
        __syncthreads();
        a = 0.f;
        for (int i = tid; i < 1024; i += 256) { float w = Wv[h * 1024 + i]; a += w * w; }
        red[tid] = a; __syncthreads();
        for (int s = 128; s > 0; s >>= 1) { if (tid < s) red[tid] += red[tid + s]; __syncthreads(); }
        if (tid == 0) sv[h] = red[0];
        __syncthreads();
    }
    float a = 0.f;
    for (int i = tid; i < 4096; i += 256) { float w = Wo[i]; a += w * w; }
    red[tid] = a; __syncthreads();
    for (int s = 128; s > 0; s >>= 1) { if (tid < s) red[tid] += red[tid + s]; __syncthreads(); }
    if (tid == 0) {
        double z = 2304.0 / 2.718281828459045;
        double w = log(z) - log(log(z));
        for (int it = 0; it < 30; it++) {
            double ew = exp(w);
            w = w - (w * ew - z) / (ew * (w + 1.0));
        }
        float phi = (float)w;
        float term = sqrtf(sq[0] * sv[0] + sq[1] * sv[1] + sq[2] * sv[2] + sq[3] * sv[3]);
        d_bound[0] = sqrtf(2304.f / 64.f) * (4.f * phi + 1.f) * term * sqrtf(red[0]);
    }
}

// ---------------- K1: flash with bf16 mma.sync -------------------------------
// logit2 = 0.5*log2e*(q.k) - ql_n - ql_m ; p = exp2(logit2) <= ~1
__global__ void __launch_bounds__(256) k_flash() {
    int bh = blockIdx.y;
    int n0 = blockIdx.x * 64;
    int tid = threadIdx.x;
    int w = tid >> 5, lane = tid & 31;
    int rw = (w & 3) * 16;        // warp row base within tile
    int cl = w >> 2;              // column half (0/1)
    int grp = lane >> 3, lr = lane & 7;

    __shared__ __align__(16) __nv_bfloat16 sQ[64 * 24];   // rows n, pitch 24
    __shared__ __align__(16) __nv_bfloat16 sK[64 * 24];   // rows m, pitch 24
    __shared__ __align__(16) __nv_bfloat16 sZ[16 * 72];   // rows c, pitch 72
    __shared__ float sKn[64];
    __shared__ float sRed[4 * 32 * 10];

    const uint4* qb4 = (const uint4*)d_qb + (size_t)bh * Nn * 2;
    const __nv_bfloat16* zb = d_zb + (size_t)bh * DHd * Nn;
    const float* qnb = d_qn + (size_t)bh * Nn;

    // ---- stage Q tile ----
    int krow = tid >> 1, khalf = tid & 1;
    if (tid < 128)
        *(uint4*)(sQ + krow * 24 + khalf * 8) = qb4[(n0 + krow) * 2 + khalf];

    // ---- prefetch tile 0 ----
    uint4 pK, pZ;
    float pN = 0.f;
    int zc = (tid - 128) >> 3, zseg = (tid - 128) & 7;
    if (tid < 128) pK = qb4[krow * 2 + khalf];
    else           pZ = *(const uint4*)(zb + (size_t)zc * Nn + zseg * 8);
    if (tid < 64)  pN = qnb[tid];

    __syncthreads();

    // ---- Q fragment (held in regs whole kernel) + row bias ----
    uint32_t qa0, qa1, qa2, qa3;
    {
        uint32_t addr = smem_u32(sQ) + ((rw + (grp & 1) * 8 + lr) * 24 + (grp >> 1) * 8) * 2;
        ldsm4(qa0, qa1, qa2, qa3, addr);
    }
    float nq0 = -qnb[n0 + rw + (lane >> 2)];
    float nq1 = -qnb[n0 + rw + (lane >> 2) + 8];

    // ldmatrix addresses (loop-invariant)
    uint32_t AK0 = smem_u32(sK) + ((32 * cl + (grp >> 1) * 8 + lr) * 24 + (grp & 1) * 8) * 2;
    uint32_t AK1 = AK0 + 16 * 24 * 2;
    uint32_t AZ0 = smem_u32(sZ) + ((grp >> 1) * 8 + lr) * 72 * 2 + (32 * cl + (grp & 1) * 8) * 2;
    uint32_t AZ1 = AZ0 + 16 * 2;

    float O[2][4];
#pragma unroll
    for (int u = 0; u < 2; u++)
#pragma unroll
        for (int k = 0; k < 4; k++) O[u][k] = 0.f;
    float li0 = 0.f, li1 = 0.f;

    for (int t = 0; t < 36; t++) {
        __syncthreads();
        if (tid < 128) *(uint4*)(sK + krow * 24 + khalf * 8) = pK;
        else           *(uint4*)(sZ + zc * 72 + zseg * 8) = pZ;
        if (tid < 64) sKn[tid] = pN;
        if (t < 35) {
            int m0 = (t + 1) * 64;
            if (tid < 128) pK = qb4[(m0 + krow) * 2 + khalf];
            else           pZ = *(const uint4*)(zb + (size_t)zc * Nn + m0 + zseg * 8);
            if (tid < 64)  pN = qnb[m0 + tid];
        }
        __syncthreads();

        // ---- K fragments ----
        uint32_t kf[4][2];
        {
            uint32_t r0, r1, r2, r3;
            ldsm4(r0, r1, r2, r3, AK0);
            kf[0][0] = r0; kf[0][1] = r1; kf[1][0] = r2; kf[1][1] = r3;
            ldsm4(r0, r1, r2, r3, AK1);
            kf[2][0] = r0; kf[2][1] = r1; kf[3][0] = r2; kf[3][1] = r3;
        }

        // ---- S mmas + softmax ----
        float p[4][4];
#pragma unroll
        for (int j = 0; j < 4; j++) {
            float2 kn2 = *(const float2*)&sKn[32 * cl + 8 * j + 2 * (lane & 3)];
            float d0, d1, d2, d3;
            mma16816(d0, d1, d2, d3, qa0, qa1, qa2, qa3, kf[j][0], kf[j][1],
                     nq0 - kn2.x, nq0 - kn2.y, nq1 - kn2.x, nq1 - kn2.y);
            p[j][0] = ex2(d0); p[j][1] = ex2(d1);
            p[j][2] = ex2(d2); p[j][3] = ex2(d3);
            li0 += p[j][0] + p[j][1];
            li1 += p[j][2] + p[j][3];
        }

        // ---- PV mmas ----
#pragma unroll
        for (int s = 0; s < 2; s++) {
            uint32_t z0, z1, z2, z3;
            ldsm4(z0, z1, z2, z3, s ? AZ1 : AZ0);
            uint32_t a0 = cvt2(p[2 * s][0], p[2 * s][1]);
            uint32_t a1 = cvt2(p[2 * s][2], p[2 * s][3]);
            uint32_t a2 = cvt2(p[2 * s + 1][0], p[2 * s + 1][1]);
            uint32_t a3 = cvt2(p[2 * s + 1][2], p[2 * s + 1][3]);
            mma16816(O[0][0], O[0][1], O[0][2], O[0][3], a0, a1, a2, a3, z0, z1,
                     O[0][0], O[0][1], O[0][2], O[0][3]);
            mma16816(O[1][0], O[1][1], O[1][2], O[1][3], a0, a1, a2, a3, z2, z3,
                     O[1][0], O[1][1], O[1][2], O[1][3]);
        }
    }

    // quad-reduce li (lanes within a quad hold disjoint column partials)
    li0 += __shfl_xor_sync(0xffffffffu, li0, 1);
    li0 += __shfl_xor_sync(0xffffffffu, li0, 2);
    li1 += __shfl_xor_sync(0xffffffffu, li1, 1);
    li1 += __shfl_xor_sync(0xffffffffu, li1, 2);

    // cross-column-half reduction via smem
    __syncthreads();
    if (cl == 1) {
        float* dst = &sRed[((w & 3) * 32 + lane) * 10];
#pragma unroll
        for (int k = 0; k < 4; k++) { dst[k] = O[0][k]; dst[4 + k] = O[1][k]; }
        dst[8] = li0; dst[9] = li1;
    }
    __syncthreads();
    if (cl == 0) {
        const float* src = &sRed[((w & 3) * 32 + lane) * 10];
#pragma unroll
        for (int k = 0; k < 4; k++) { O[0][k] += src[k]; O[1][k] += src[4 + k]; }
        li0 += src[8]; li1 += src[9];
        float i0 = 1.f / li0, i1 = 1.f / li1;
        int r = n0 + rw + (lane >> 2);
        int cb = 2 * (lane & 3);
        float* ur0 = d_u + ((size_t)bh * Nn + r) * 16;
        float* ur1 = d_u + ((size_t)bh * Nn + r + 8) * 16;
        *(float2*)(ur0 + cb)     = make_float2(O[0][0] * i0, O[0][1] * i0);
        *(float2*)(ur0 + cb + 8) = make_float2(O[1][0] * i0, O[1][1] * i0);
        *(float2*)(ur1 + cb)     = make_float2(O[0][2] * i1, O[0][3] * i1);
        *(float2*)(ur1 + cb + 8) = make_float2(O[1][2] * i1, O[1][3] * i1);
    }
}

// ---------------- K_g: g = U @ R^T / 4 --------------------------------------
__global__ void __launch_bounds__(256) k_g(const float* __restrict__ Wq) {
    int bh = blockIdx.y;
    int h = bh & 3;
    int n0 = blockIdx.x * 64;
    int tid = threadIdx.x, ty = tid >> 4, tx = tid & 15;

    __shared__ float sUt[16][64];
    __shared__ float sRt[16][64];
    {
        int n = tid & 63, cg = tid >> 6;
        float4 v = *(const float4*)(d_u + ((size_t)bh * Nn + n0 + n) * DHd + cg * 4);
        sUt[cg * 4 + 0][n] = v.x; sUt[cg * 4 + 1][n] = v.y;
        sUt[cg * 4 + 2][n] = v.z; sUt[cg * 4 + 3][n] = v.w;
        int dd = tid & 63;
        float4 r = *(const float4*)(Wq + h * 1024 + dd * 16 + cg * 4);
        sRt[cg * 4 + 0][dd] = r.x; sRt[cg * 4 + 1][dd] = r.y;
        sRt[cg * 4 + 2][dd] = r.z; sRt[cg * 4 + 3][dd] = r.w;
    }
    __syncthreads();

    float acc[4][4];
#pragma unroll
    for (int i = 0; i < 4; i++)
#pragma unroll
        for (int j = 0; j < 4; j++) acc[i][j] = 0.f;
#pragma unroll
    for (int c = 0; c < 16; c++) {
        float4 uv = *(const float4*)(&sUt[c][ty * 4]);
        float4 rv = *(const float4*)(&sRt[c][tx * 4]);
        float u[4] = {uv.x, uv.y, uv.z, uv.w};
        float r[4] = {rv.x, rv.y, rv.z, rv.w};
#pragma unroll
        for (int i = 0; i < 4; i++)
#pragma unroll
            for (int j = 0; j < 4; j++) acc[i][j] += u[i] * r[j];
    }
#pragma unroll
    for (int i = 0; i < 4; i++) {
        float4 w = make_float4(acc[i][0] * 0.25f, acc[i][1] * 0.25f,
                               acc[i][2] * 0.25f, acc[i][3] * 0.25f);
        *(float4*)(d_g + ((size_t)bh * Nn + n0 + ty * 4 + i) * 64 + tx * 4) = w;
    }
}

// ---------------- K_v: v[bh][k][vc] = Wv . f_img + bv -----------------------
__global__ void __launch_bounds__(256) k_v(const float* __restrict__ Wv,
                                           const float* __restrict__ bv) {
    int bh = blockIdx.y;
    int h = bh & 3;
    int vc = blockIdx.x * 256 + threadIdx.x;
    __shared__ float sw[DHd * Dd];
    for (int i = threadIdx.x; i < 1024; i += 256) sw[i] = Wv[h * 1024 + i];
    __syncthreads();
    int a = vc >> 6;
    int r = vc & 63;
    const float* gb = d_g + (size_t)bh * Nn * 64;
    float gv[64];
#pragma unroll
    for (int dd = 0; dd < 64; dd++) gv[dd] = gb[(36 * dd + a) * 64 + r];
#pragma unroll
    for (int k = 0; k < 16; k++) {
        float acc = bv[h * 16 + k];
        const float* w = sw + k * 64;
#pragma unroll
        for (int dd = 0; dd < 64; dd++) acc += w[dd] * gv[dd];
        d_v[((size_t)bh * 16 + k) * Nn + vc] = acc;
    }
}

// ---------------- K_out: cat gather + Wo gemm + residual --------------------
__global__ void __launch_bounds__(256) k_out(const float* __restrict__ Wo,
                                             const float* __restrict__ bo,
                                             const float* __restrict__ gamma,
                                             const float* __restrict__ x,
                                             float* __restrict__ out) {
    int b = blockIdx.y;
    int n0 = blockIdx.x * 64;
    int a = n0 >> 6;
    int tid = threadIdx.x, ty = tid >> 4, tx = tid & 15;
    __shared__ __align__(16) float sC[64][68];
    __shared__ float sW[64][64];
    for (int i = tid; i < 4096; i += 256) {
        int dd = i >> 6, j = i & 63;
        int h = j >> 4, kk = j & 15;
        int vidx = (36 * dd + a) * 16 + kk;
        int vr = vidx / Nn;
        int vcol = vidx - vr * Nn;
        sC[dd][j] = d_v[((size_t)(b * Hh + h) * 16 + vr) * Nn + vcol];
    }
    for (int i = tid; i < 4096; i += 256) sW[i >> 6][i & 63] = Wo[i];
    __syncthreads();
    float acc[4][4];
#pragma unroll
    for (int i = 0; i < 4; i++)
#pragma unroll
        for (int c = 0; c < 4; c++) acc[i][c] = 0.f;
#pragma unroll 4
    for (int dd = 0; dd < 64; dd++) {
        float wv[4];
#pragma unroll
        for (int i = 0; i < 4; i++) wv[i] = sW[ty + 16 * i][dd];
        float4 cv = *(const float4*)(&sC[dd][tx * 4]);
#pragma unroll
        for (int i = 0; i < 4; i++) {
            acc[i][0] += wv[i] * cv.x;
            acc[i][1] += wv[i] * cv.y;
            acc[i][2] += wv[i] * cv.z;
            acc[i][3] += wv[i] * cv.w;
        }
    }
    float scale = gamma[0] / d_bound[0];
#pragma unroll
    for (int i = 0; i < 4; i++) {
        int o = ty + 16 * i;
        float bb = bo[o];
        size_t base = ((size_t)b * 64 + o) * Nn + n0 + tx * 4;
        float4 xin = *(const float4*)(&x[base]);
        float4 r;
        r.x = scale * (acc[i][0] + bb) + xin.x;
        r.y = scale * (acc[i][1] + bb) + xin.y;
        r.z = scale * (acc[i][2] + bb) + xin.z;
        r.w = scale * (acc[i][3] + bb) + xin.w;
        *(float4*)(&out[base]) = r;
    }
}

// ---------------- launch -----------------------------------------------------
extern "C" void kernel_launch(void* const* d_in, const int* in_sizes, int n_in,
                              void* d_out, int out_size) {
    const float* x     = (const float*)d_in[0];
    const float* Wq    = (const float*)d_in[1];
    const float* bq    = (const float*)d_in[2];
    const float* Wv    = (const float*)d_in[3];
    const float* bv    = (const float*)d_in[4];
    const float* Wo    = (const float*)d_in[5];
    const float* bo    = (const float*)d_in[6];
    const float* gamma = (const float*)d_in[7];
    float* out = (float*)d_out;

    k_q    <<<dim3(Nn / 128, Bb, Hh), 128>>>(x, Wq, bq);
    k_z    <<<dim3(Nn / 256, Bb, Hh), 256>>>(x, Wq);
    k_bound<<<1, 256>>>(Wq, Wv, Wo);
    k_flash<<<dim3(Nn / 64, BHh), 256>>>();
    k_g    <<<dim3(Nn / 64, BHh), 256>>>(Wq);
    k_v    <<<dim3(Nn / 256, BHh), 256>>>(Wv, bv);
    k_out  <<<dim3(Nn / 64, Bb), 256>>>(Wo, bo, gamma, x, out);
}

// round 6
// speedup vs baseline: 2.4624x; 1.0638x over previous
#include <cuda_runtime.h>
#include <cuda_bf16.h>
#include <math.h>
#include <stdint.h>

#define Bb   4
#define Dd   64
#define Hh   4
#define DHd  16
#define Nn   2304
#define BHh  16   // B*heads

#define LOG2E 1.4426950408889634f
#define SC    0.8493218593f   // sqrt(0.5*log2e)

// ---------------- scratch (device globals) ----------------------------------
__device__ uint32_t d_qb[BHh * Nn * 8];          // q bf16x2: [bh][n][k/2], scaled by SC
__device__ float d_qn[BHh * Nn];                 // 0.25*log2e*||q||^2
__device__ __nv_bfloat16 d_zb[BHh * DHd * Nn];   // Z bf16: [bh][c][m]
__device__ float d_u[BHh * Nn * DHd];            // U = softmax(P) @ Z   [bh][n][c]
__device__ float d_v[BHh * DHd * Nn];            // v[bh][k][vc]
__device__ float d_bound[1];

__device__ __forceinline__ float ex2(float a) {
    float r;
    asm("ex2.approx.ftz.f32 %0, %1;" : "=f"(r) : "f"(a));
    return r;
}
__device__ __forceinline__ uint32_t cvt2(float lo, float hi) {
    uint32_t r;
    asm("cvt.rn.bf16x2.f32 %0, %1, %2;" : "=r"(r) : "f"(hi), "f"(lo));
    return r;
}
__device__ __forceinline__ uint32_t smem_u32(const void* p) {
    return (uint32_t)__cvta_generic_to_shared(p);
}
__device__ __forceinline__ void ldsm4(uint32_t& r0, uint32_t& r1, uint32_t& r2, uint32_t& r3,
                                      uint32_t addr) {
    asm volatile("ldmatrix.sync.aligned.m8n8.x4.shared.b16 {%0,%1,%2,%3}, [%4];"
                 : "=r"(r0), "=r"(r1), "=r"(r2), "=r"(r3) : "r"(addr));
}
__device__ __forceinline__ void mma16816(float& d0, float& d1, float& d2, float& d3,
                                         uint32_t a0, uint32_t a1, uint32_t a2, uint32_t a3,
                                         uint32_t b0, uint32_t b1,
                                         float c0, float c1, float c2, float c3) {
    asm volatile("mma.sync.aligned.m16n8k16.row.col.f32.bf16.bf16.f32 "
                 "{%0,%1,%2,%3},{%4,%5,%6,%7},{%8,%9},{%10,%11,%12,%13};"
                 : "=f"(d0), "=f"(d1), "=f"(d2), "=f"(d3)
                 : "r"(a0), "r"(a1), "r"(a2), "r"(a3), "r"(b0), "r"(b1),
                   "f"(c0), "f"(c1), "f"(c2), "f"(c3));
}

// ---------------- K_qz: z<4 -> q head z; z>=4 -> Z head z-4 ------------------
__global__ void __launch_bounds__(128) k_qz(const float* __restrict__ x,
                                            const float* __restrict__ Wq,
                                            const float* __restrict__ bq) {
    __shared__ float sW[DHd * Dd];
    int tid = threadIdx.x;
    int z = blockIdx.z;
    int b = blockIdx.y;

    if (z < 4) {
        int h = z;
        for (int i = tid; i < 1024; i += 128) sW[i] = Wq[h * 1024 + i];
        __syncthreads();
        int n = blockIdx.x * 128 + tid;
        int bh = b * Hh + h;
        const float* xb = x + b * Dd * Nn;
        float xv[Dd];
#pragma unroll
        for (int d = 0; d < Dd; d++) xv[d] = xb[d * Nn + n];
        float qv[DHd];
        float qn = 0.f;
#pragma unroll
        for (int k = 0; k < DHd; k++) {
            float acc = bq[h * DHd + k];
            const float* w = sW + k * Dd;
#pragma unroll
            for (int d = 0; d < Dd; d++) acc += w[d] * xv[d];
            qv[k] = acc;
            qn += acc * acc;
        }
        uint32_t pk[8];
#pragma unroll
        for (int i = 0; i < 8; i++) pk[i] = cvt2(SC * qv[2 * i], SC * qv[2 * i + 1]);
        uint4* dst = (uint4*)(d_qb + ((size_t)bh * Nn + n) * 8);
        dst[0] = make_uint4(pk[0], pk[1], pk[2], pk[3]);
        dst[1] = make_uint4(pk[4], pk[5], pk[6], pk[7]);
        d_qn[(size_t)bh * Nn + n] = qn * (0.25f * LOG2E);
    } else {
        int h = z - 4;
        for (int i = tid; i < 1024; i += 128) sW[i] = Wq[h * 1024 + i];
        __syncthreads();
        int m = blockIdx.x * 128 + tid;
        int bh = b * Hh + h;
        const float* xr = x + (size_t)b * Dd * Nn + (size_t)m * Dd;
        float acc[DHd];
#pragma unroll
        for (int c = 0; c < DHd; c++) acc[c] = 0.f;
#pragma unroll
        for (int dc = 0; dc < 16; dc++) {
            float4 v = *(const float4*)(xr + dc * 4);
            float xd[4] = {v.x, v.y, v.z, v.w};
#pragma unroll
            for (int q = 0; q < 4; q++) {
                const float4* rr = (const float4*)(sW + (dc * 4 + q) * 16);
#pragma unroll
                for (int cc = 0; cc < 4; cc++) {
                    float4 rv = rr[cc];
                    acc[cc * 4 + 0] += xd[q] * rv.x;
                    acc[cc * 4 + 1] += xd[q] * rv.y;
                    acc[cc * 4 + 2] += xd[q] * rv.z;
                    acc[cc * 4 + 3] += xd[q] * rv.w;
                }
            }
        }
#pragma unroll
        for (int c = 0; c < DHd; c++)
            d_zb[((size_t)bh * DHd + c) * Nn + m] = __float2bfloat16_rn(acc[c]);
    }
}

// ---------------- K_bound ----------------------------------------------------
__global__ void k_bound(const float* __restrict__ Wq,
                        const float* __restrict__ Wv,
                        const float* __restrict__ Wo) {
    __shared__ float red[256];
    __shared__ float sq[Hh], sv[Hh];
    int tid = threadIdx.x;
    for (int h = 0; h < Hh; h++) {
        float a = 0.f;
        for (int i = tid; i < 1024; i += 256) { float w = Wq[h * 1024 + i]; a += w * w; }
        red[tid] = a; __syncthreads();
        for (int s = 128; s > 0; s >>= 1) { if (tid < s) red[tid] += red[tid + s]; __syncthreads(); }
        if (tid == 0) sq[h] = red[0];
        __syncthreads();
        a = 0.f;
        for (int i = tid; i < 1024; i += 256) { float w = Wv[h * 1024 + i]; a += w * w; }
        red[tid] = a; __syncthreads();
        for (int s = 128; s > 0; s >>= 1) { if (tid < s) red[tid] += red[tid + s]; __syncthreads(); }
        if (tid == 0) sv[h] = red[0];
        __syncthreads();
    }
    float a = 0.f;
    for (int i = tid; i < 4096; i += 256) { float w = Wo[i]; a += w * w; }
    red[tid] = a; __syncthreads();
    for (int s = 128; s > 0; s >>= 1) { if (tid < s) red[tid] += red[tid + s]; __syncthreads(); }
    if (tid == 0) {
        double z = 2304.0 / 2.718281828459045;
        double w = log(z) - log(log(z));
        for (int it = 0; it < 30; it++) {
            double ew = exp(w);
            w = w - (w * ew - z) / (ew * (w + 1.0));
        }
        float phi = (float)w;
        float term = sqrtf(sq[0] * sv[0] + sq[1] * sv[1] + sq[2] * sv[2] + sq[3] * sv[3]);
        d_bound[0] = sqrtf(2304.f / 64.f) * (4.f * phi + 1.f) * term * sqrtf(red[0]);
    }
}

// ---------------- K1: flash (128 q-rows/block, warp owns 16x64 strip) --------
__global__ void __launch_bounds__(256) k_flash() {
    int bh = blockIdx.y;
    int n0 = blockIdx.x * 128;
    int tid = threadIdx.x;
    int w = tid >> 5, lane = tid & 31;
    int grp = lane >> 3, lr = lane & 7;

    __shared__ __align__(16) __nv_bfloat16 sQ[128 * 24];  // rows n, pitch 24
    __shared__ __align__(16) __nv_bfloat16 sK[64 * 24];   // rows m, pitch 24
    __shared__ __align__(16) __nv_bfloat16 sZ[16 * 72];   // rows c, pitch 72
    __shared__ float sKn[64];

    const uint4* qb4 = (const uint4*)d_qb + (size_t)bh * Nn * 2;
    const __nv_bfloat16* zb = d_zb + (size_t)bh * DHd * Nn;
    const float* qnb = d_qn + (size_t)bh * Nn;

    // stage Q tile (128 rows, one uint4 per thread x2? -> 256 uint4, 1/thread)
    {
        int row = tid >> 1, half = tid & 1;
        *(uint4*)(sQ + row * 24 + half * 8) = qb4[(size_t)(n0 + row) * 2 + half];
    }

    // prefetch tile 0
    uint4 pK, pZ;
    float pN = 0.f;
    int krow = tid >> 1, khalf = tid & 1;
    int zc = (tid - 128) >> 3, zseg = (tid - 128) & 7;
    if (tid < 128) pK = qb4[krow * 2 + khalf];
    else           pZ = *(const uint4*)(zb + (size_t)zc * Nn + zseg * 8);
    if (tid < 64)  pN = qnb[tid];

    __syncthreads();

    // Q fragment (held whole kernel)
    uint32_t qa0, qa1, qa2, qa3;
    {
        uint32_t addr = smem_u32(sQ) + ((w * 16 + (grp & 1) * 8 + lr) * 24 + (grp >> 1) * 8) * 2;
        ldsm4(qa0, qa1, qa2, qa3, addr);
    }
    float nq0 = -qnb[n0 + w * 16 + (lane >> 2)];
    float nq1 = -qnb[n0 + w * 16 + (lane >> 2) + 8];

    uint32_t AKb = smem_u32(sK) + (((grp >> 1) * 8 + lr) * 24 + (grp & 1) * 8) * 2;
    uint32_t AZb = smem_u32(sZ) + ((grp >> 1) * 8 + lr) * 144 + ((grp & 1) * 8) * 2;

    float O[2][4];
#pragma unroll
    for (int u = 0; u < 2; u++)
#pragma unroll
        for (int k = 0; k < 4; k++) O[u][k] = 0.f;
    float li0 = 0.f, li1 = 0.f;

    for (int t = 0; t < 36; t++) {
        __syncthreads();
        if (tid < 128) *(uint4*)(sK + krow * 24 + khalf * 8) = pK;
        else           *(uint4*)(sZ + zc * 72 + zseg * 8) = pZ;
        if (tid < 64) sKn[tid] = pN;
        if (t < 35) {
            int m0 = (t + 1) * 64;
            if (tid < 128) pK = qb4[(size_t)(m0 + krow) * 2 + khalf];
            else           pZ = *(const uint4*)(zb + (size_t)zc * Nn + m0 + zseg * 8);
            if (tid < 64)  pN = qnb[m0 + tid];
        }
        __syncthreads();

        // K fragments: 4 ldsm4 over 64 m-rows
        uint32_t kf[8][2];
#pragma unroll
        for (int s = 0; s < 4; s++) {
            uint32_t r0, r1, r2, r3;
            ldsm4(r0, r1, r2, r3, AKb + s * 768);
            kf[2 * s][0] = r0; kf[2 * s][1] = r1;
            kf[2 * s + 1][0] = r2; kf[2 * s + 1][1] = r3;
        }

        // S mmas + softmax (8 x m16n8k16 covering 64 cols)
        float p[8][4];
#pragma unroll
        for (int j = 0; j < 8; j++) {
            float2 kn2 = *(const float2*)&sKn[8 * j + 2 * (lane & 3)];
            float d0, d1, d2, d3;
            mma16816(d0, d1, d2, d3, qa0, qa1, qa2, qa3, kf[j][0], kf[j][1],
                     nq0 - kn2.x, nq0 - kn2.y, nq1 - kn2.x, nq1 - kn2.y);
            p[j][0] = ex2(d0); p[j][1] = ex2(d1);
            p[j][2] = ex2(d2); p[j][3] = ex2(d3);
            li0 += p[j][0] + p[j][1];
            li1 += p[j][2] + p[j][3];
        }

        // PV mmas: 4 k-chunks x 2 n-chunks
#pragma unroll
        for (int s = 0; s < 4; s++) {
            uint32_t z0, z1, z2, z3;
            ldsm4(z0, z1, z2, z3, AZb + s * 32);
            uint32_t a0 = cvt2(p[2 * s][0], p[2 * s][1]);
            uint32_t a1 = cvt2(p[2 * s][2], p[2 * s][3]);
            uint32_t a2 = cvt2(p[2 * s + 1][0], p[2 * s + 1][1]);
            uint32_t a3 = cvt2(p[2 * s + 1][2], p[2 * s + 1][3]);
            mma16816(O[0][0], O[0][1], O[0][2], O[0][3], a0, a1, a2, a3, z0, z1,
                     O[0][0], O[0][1], O[0][2], O[0][3]);
            mma16816(O[1][0], O[1][1], O[1][2], O[1][3], a0, a1, a2, a3, z2, z3,
                     O[1][0], O[1][1], O[1][2], O[1][3]);
        }
    }

    // quad-reduce li (lanes in quad hold disjoint columns)
    li0 += __shfl_xor_sync(0xffffffffu, li0, 1);
    li0 += __shfl_xor_sync(0xffffffffu, li0, 2);
    li1 += __shfl_xor_sync(0xffffffffu, li1, 1);
    li1 += __shfl_xor_sync(0xffffffffu, li1, 2);

    float i0 = 1.f / li0, i1 = 1.f / li1;
    int r = n0 + w * 16 + (lane >> 2);
    int cb = 2 * (lane & 3);
    float* ur0 = d_u + ((size_t)bh * Nn + r) * 16;
    float* ur1 = d_u + ((size_t)bh * Nn + r + 8) * 16;
    *(float2*)(ur0 + cb)     = make_float2(O[0][0] * i0, O[0][1] * i0);
    *(float2*)(ur0 + cb + 8) = make_float2(O[1][0] * i0, O[1][1] * i0);
    *(float2*)(ur1 + cb)     = make_float2(O[0][2] * i1, O[0][3] * i1);
    *(float2*)(ur1 + cb + 8) = make_float2(O[1][2] * i1, O[1][3] * i1);
}

// ---------------- K_gv: fused g=U@R^T/4 and v=Wv@f_img+bv -------------------
// v[bh][k][a*64+r] = bv[k] + 0.25 * sum_c R[r][c] * M[k][c],
// M[k][c] = sum_dd Wv[k][dd] * U[bh][36*dd+a][c]
__global__ void __launch_bounds__(256) k_gv(const float* __restrict__ Wq,
                                            const float* __restrict__ Wv,
                                            const float* __restrict__ bv) {
    int bh = blockIdx.y;
    int h = bh & 3;
    int a = blockIdx.x;
    int tid = threadIdx.x;

    __shared__ float sT[64][17];   // T[dd][c] = U[36dd+a][c]
    __shared__ float sWv[1024];    // Wv[k][dd]
    __shared__ float sR[64][17];   // R[r][c]
    __shared__ float sM[16][17];

    {
        int dd = tid >> 2, cg = tid & 3;
        float4 v = *(const float4*)(d_u + ((size_t)bh * Nn + 36 * dd + a) * 16 + cg * 4);
        sT[dd][cg * 4 + 0] = v.x; sT[dd][cg * 4 + 1] = v.y;
        sT[dd][cg * 4 + 2] = v.z; sT[dd][cg * 4 + 3] = v.w;
        float4 rv = *(const float4*)(Wq + h * 1024 + dd * 16 + cg * 4);
        sR[dd][cg * 4 + 0] = rv.x; sR[dd][cg * 4 + 1] = rv.y;
        sR[dd][cg * 4 + 2] = rv.z; sR[dd][cg * 4 + 3] = rv.w;
    }
    for (int i = tid; i < 1024; i += 256) sWv[i] = Wv[h * 1024 + i];
    __syncthreads();

    // M[k][c], one element per thread
    {
        int k = tid >> 4, c = tid & 15;
        float acc = 0.f;
#pragma unroll
        for (int dd = 0; dd < 64; dd++) acc += sWv[k * 64 + dd] * sT[dd][c];
        sM[k][c] = acc;
    }
    __syncthreads();

    // v: 4 k per thread
    {
        int r = tid & 63, kg = tid >> 6;
        float vacc[4] = {0.f, 0.f, 0.f, 0.f};
#pragma unroll
        for (int c = 0; c < 16; c++) {
            float rc = sR[r][c];
            vacc[0] += sM[kg * 4 + 0][c] * rc;
            vacc[1] += sM[kg * 4 + 1][c] * rc;
            vacc[2] += sM[kg * 4 + 2][c] * rc;
            vacc[3] += sM[kg * 4 + 3][c] * rc;
        }
#pragma unroll
        for (int kk = 0; kk < 4; kk++) {
            int k = kg * 4 + kk;
            d_v[((size_t)bh * 16 + k) * Nn + a * 64 + r] = bv[h * 16 + k] + 0.25f * vacc[kk];
        }
    }
}

// ---------------- K_out: cat gather + Wo gemm + residual --------------------
__global__ void __launch_bounds__(256) k_out(const float* __restrict__ Wo,
                                             const float* __restrict__ bo,
                                             const float* __restrict__ gamma,
                                             const float* __restrict__ x,
                                             float* __restrict__ out) {
    int b = blockIdx.y;
    int n0 = blockIdx.x * 64;
    int a = n0 >> 6;
    int tid = threadIdx.x, ty = tid >> 4, tx = tid & 15;
    __shared__ __align__(16) float sC[64][68];
    __shared__ float sW[64][64];
    for (int i = tid; i < 4096; i += 256) {
        int dd = i >> 6, j = i & 63;
        int h = j >> 4, kk = j & 15;
        int vidx = (36 * dd + a) * 16 + kk;
        int vr = vidx / Nn;
        int vcol = vidx - vr * Nn;
        sC[dd][j] = d_v[((size_t)(b * Hh + h) * 16 + vr) * Nn + vcol];
    }
    for (int i = tid; i < 4096; i += 256) sW[i >> 6][i & 63] = Wo[i];
    __syncthreads();
    float acc[4][4];
#pragma unroll
    for (int i = 0; i < 4; i++)
#pragma unroll
        for (int c = 0; c < 4; c++) acc[i][c] = 0.f;
#pragma unroll 4
    for (int dd = 0; dd < 64; dd++) {
        float wv[4];
#pragma unroll
        for (int i = 0; i < 4; i++) wv[i] = sW[ty + 16 * i][dd];
        float4 cv = *(const float4*)(&sC[dd][tx * 4]);
#pragma unroll
        for (int i = 0; i < 4; i++) {
            acc[i][0] += wv[i] * cv.x;
            acc[i][1] += wv[i] * cv.y;
            acc[i][2] += wv[i] * cv.z;
            acc[i][3] += wv[i] * cv.w;
        }
    }
    float scale = gamma[0] / d_bound[0];
#pragma unroll
    for (int i = 0; i < 4; i++) {
        int o = ty + 16 * i;
        float bb = bo[o];
        size_t base = ((size_t)b * 64 + o) * Nn + n0 + tx * 4;
        float4 xin = *(const float4*)(&x[base]);
        float4 r;
        r.x = scale * (acc[i][0] + bb) + xin.x;
        r.y = scale * (acc[i][1] + bb) + xin.y;
        r.z = scale * (acc[i][2] + bb) + xin.z;
        r.w = scale * (acc[i][3] + bb) + xin.w;
        *(float4*)(&out[base]) = r;
    }
}

// ---------------- launch -----------------------------------------------------
extern "C" void kernel_launch(void* const* d_in, const int* in_sizes, int n_in,
                              void* d_out, int out_size) {
    const float* x     = (const float*)d_in[0];
    const float* Wq    = (const float*)d_in[1];
    const float* bq    = (const float*)d_in[2];
    const float* Wv    = (const float*)d_in[3];
    const float* bv    = (const float*)d_in[4];
    const float* Wo    = (const float*)d_in[5];
    const float* bo    = (const float*)d_in[6];
    const float* gamma = (const float*)d_in[7];
    float* out = (float*)d_out;

    k_qz   <<<dim3(Nn / 128, Bb, 8), 128>>>(x, Wq, bq);
    k_bound<<<1, 256>>>(Wq, Wv, Wo);
    k_flash<<<dim3(Nn / 128, BHh), 256>>>();
    k_gv   <<<dim3(36, BHh), 256>>>(Wq, Wv, bv);
    k_out  <<<dim3(Nn / 64, Bb), 256>>>(Wo, bo, gamma, x, out);
}

// round 7
// speedup vs baseline: 2.7407x; 1.1130x over previous
#include <cuda_runtime.h>
#include <cuda_bf16.h>
#include <math.h>
#include <stdint.h>

#define Bb   4
#define Dd   64
#define Hh   4
#define DHd  16
#define Nn   2304
#define BHh  16   // B*heads

#define LOG2E 1.4426950408889634f
#define SC    0.8493218593f   // sqrt(0.5*log2e)

// ---------------- scratch (device globals) ----------------------------------
__device__ uint32_t d_qb[BHh * Nn * 8];          // q bf16x2: [bh][n][k/2], scaled by SC
__device__ float d_qn[BHh * Nn];                 // 0.25*log2e*||q||^2
__device__ __nv_bfloat16 d_zb[BHh * DHd * Nn];   // Z bf16: [bh][c][m]
__device__ float d_u[BHh * Nn * DHd];            // U permuted: row' = (n%36)*64 + n/36
__device__ float d_v[BHh * DHd * Nn];            // v[bh][k][vc]
__device__ float d_bound[1];

__device__ __forceinline__ float ex2(float a) {
    float r;
    asm("ex2.approx.ftz.f32 %0, %1;" : "=f"(r) : "f"(a));
    return r;
}
__device__ __forceinline__ uint32_t cvt2(float lo, float hi) {
    uint32_t r;
    asm("cvt.rn.bf16x2.f32 %0, %1, %2;" : "=r"(r) : "f"(hi), "f"(lo));
    return r;
}
__device__ __forceinline__ uint32_t smem_u32(const void* p) {
    return (uint32_t)__cvta_generic_to_shared(p);
}
__device__ __forceinline__ void ldsm4(uint32_t& r0, uint32_t& r1, uint32_t& r2, uint32_t& r3,
                                      uint32_t addr) {
    asm volatile("ldmatrix.sync.aligned.m8n8.x4.shared.b16 {%0,%1,%2,%3}, [%4];"
                 : "=r"(r0), "=r"(r1), "=r"(r2), "=r"(r3) : "r"(addr));
}
__device__ __forceinline__ void mma16816(float& d0, float& d1, float& d2, float& d3,
                                         uint32_t a0, uint32_t a1, uint32_t a2, uint32_t a3,
                                         uint32_t b0, uint32_t b1,
                                         float c0, float c1, float c2, float c3) {
    asm volatile("mma.sync.aligned.m16n8k16.row.col.f32.bf16.bf16.f32 "
                 "{%0,%1,%2,%3},{%4,%5,%6,%7},{%8,%9},{%10,%11,%12,%13};"
                 : "=f"(d0), "=f"(d1), "=f"(d2), "=f"(d3)
                 : "r"(a0), "r"(a1), "r"(a2), "r"(a3), "r"(b0), "r"(b1),
                   "f"(c0), "f"(c1), "f"(c2), "f"(c3));
}

// ---------------- K_qz: z<4 -> q head z; z in[4,8) -> Z head z-4; z==8 -> bound
__global__ void __launch_bounds__(128) k_qz(const float* __restrict__ x,
                                            const float* __restrict__ Wq,
                                            const float* __restrict__ bq,
                                            const float* __restrict__ Wv,
                                            const float* __restrict__ Wo) {
    __shared__ float sW[DHd * Dd];
    int tid = threadIdx.x;
    int z = blockIdx.z;
    int b = blockIdx.y;

    if (z == 8) {
        if (blockIdx.x != 0 || blockIdx.y != 0) return;
        __shared__ float red[128];
        __shared__ float sq[Hh], sv[Hh];
        for (int h = 0; h < Hh; h++) {
            float a = 0.f;
            for (int i = tid; i < 1024; i += 128) { float w = Wq[h * 1024 + i]; a += w * w; }
            red[tid] = a; __syncthreads();
            for (int s = 64; s > 0; s >>= 1) { if (tid < s) red[tid] += red[tid + s]; __syncthreads(); }
            if (tid == 0) sq[h] = red[0];
            __syncthreads();
            a = 0.f;
            for (int i = tid; i < 1024; i += 128) { float w = Wv[h * 1024 + i]; a += w * w; }
            red[tid] = a; __syncthreads();
            for (int s = 64; s > 0; s >>= 1) { if (tid < s) red[tid] += red[tid + s]; __syncthreads(); }
            if (tid == 0) sv[h] = red[0];
            __syncthreads();
        }
        float a = 0.f;
        for (int i = tid; i < 4096; i += 128) { float w = Wo[i]; a += w * w; }
        red[tid] = a; __syncthreads();
        for (int s = 64; s > 0; s >>= 1) { if (tid < s) red[tid] += red[tid + s]; __syncthreads(); }
        if (tid == 0) {
            double zz = 2304.0 / 2.718281828459045;
            double w = log(zz) - log(log(zz));
            for (int it = 0; it < 30; it++) {
                double ew = exp(w);
                w = w - (w * ew - zz) / (ew * (w + 1.0));
            }
            float phi = (float)w;
            float term = sqrtf(sq[0] * sv[0] + sq[1] * sv[1] + sq[2] * sv[2] + sq[3] * sv[3]);
            d_bound[0] = sqrtf(2304.f / 64.f) * (4.f * phi + 1.f) * term * sqrtf(red[0]);
        }
        return;
    }

    if (z < 4) {
        int h = z;
        for (int i = tid; i < 1024; i += 128) sW[i] = Wq[h * 1024 + i];
        __syncthreads();
        int n = blockIdx.x * 128 + tid;
        int bh = b * Hh + h;
        const float* xb = x + b * Dd * Nn;
        float xv[Dd];
#pragma unroll
        for (int d = 0; d < Dd; d++) xv[d] = xb[d * Nn + n];
        float qv[DHd];
        float qn = 0.f;
#pragma unroll
        for (int k = 0; k < DHd; k++) {
            float acc = bq[h * DHd + k];
            const float* w = sW + k * Dd;
#pragma unroll
            for (int d = 0; d < Dd; d++) acc += w[d] * xv[d];
            qv[k] = acc;
            qn += acc * acc;
        }
        uint32_t pk[8];
#pragma unroll
        for (int i = 0; i < 8; i++) pk[i] = cvt2(SC * qv[2 * i], SC * qv[2 * i + 1]);
        uint4* dst = (uint4*)(d_qb + ((size_t)bh * Nn + n) * 8);
        dst[0] = make_uint4(pk[0], pk[1], pk[2], pk[3]);
        dst[1] = make_uint4(pk[4], pk[5], pk[6], pk[7]);
        d_qn[(size_t)bh * Nn + n] = qn * (0.25f * LOG2E);
    } else {
        int h = z - 4;
        for (int i = tid; i < 1024; i += 128) sW[i] = Wq[h * 1024 + i];
        __syncthreads();
        int m = blockIdx.x * 128 + tid;
        int bh = b * Hh + h;
        const float* xr = x + (size_t)b * Dd * Nn + (size_t)m * Dd;
        float acc[DHd];
#pragma unroll
        for (int c = 0; c < DHd; c++) acc[c] = 0.f;
#pragma unroll
        for (int dc = 0; dc < 16; dc++) {
            float4 v = *(const float4*)(xr + dc * 4);
            float xd[4] = {v.x, v.y, v.z, v.w};
#pragma unroll
            for (int q = 0; q < 4; q++) {
                const float4* rr = (const float4*)(sW + (dc * 4 + q) * 16);
#pragma unroll
                for (int cc = 0; cc < 4; cc++) {
                    float4 rv = rr[cc];
                    acc[cc * 4 + 0] += xd[q] * rv.x;
                    acc[cc * 4 + 1] += xd[q] * rv.y;
                    acc[cc * 4 + 2] += xd[q] * rv.z;
                    acc[cc * 4 + 3] += xd[q] * rv.w;
                }
            }
        }
#pragma unroll
        for (int c = 0; c < DHd; c++)
            d_zb[((size_t)bh * DHd + c) * Nn + m] = __float2bfloat16_rn(acc[c]);
    }
}

// ---------------- K1: flash, double-buffered, permuted U out -----------------
__global__ void __launch_bounds__(256) k_flash() {
    int bh = blockIdx.y;
    int n0 = blockIdx.x * 128;
    int tid = threadIdx.x;
    int w = tid >> 5, lane = tid & 31;
    int grp = lane >> 3, lr = lane & 7;

    __shared__ __align__(16) __nv_bfloat16 sQ[128 * 24];     // rows n, pitch 24
    __shared__ __align__(16) __nv_bfloat16 sK[2][64 * 24];   // rows m, pitch 24
    __shared__ __align__(16) __nv_bfloat16 sZ[2][16 * 72];   // rows c, pitch 72
    __shared__ float sKn[2][64];

    const uint4* qb4 = (const uint4*)d_qb + (size_t)bh * Nn * 2;
    const __nv_bfloat16* zb = d_zb + (size_t)bh * DHd * Nn;
    const float* qnb = d_qn + (size_t)bh * Nn;

    int krow = tid >> 1, khalf = tid & 1;
    int zc = (tid - 128) >> 3, zseg = (tid - 128) & 7;

    // stage Q tile + tile 0 into buf 0
    {
        int row = tid >> 1, half = tid & 1;
        *(uint4*)(sQ + row * 24 + half * 8) = qb4[(size_t)(n0 + row) * 2 + half];
    }
    if (tid < 128) *(uint4*)(sK[0] + krow * 24 + khalf * 8) = qb4[krow * 2 + khalf];
    else           *(uint4*)(sZ[0] + zc * 72 + zseg * 8) = *(const uint4*)(zb + (size_t)zc * Nn + zseg * 8);
    if (tid < 64)  sKn[0][tid] = qnb[tid];
    __syncthreads();

    // Q fragment (held whole kernel)
    uint32_t qa0, qa1, qa2, qa3;
    {
        uint32_t addr = smem_u32(sQ) + ((w * 16 + (grp & 1) * 8 + lr) * 24 + (grp >> 1) * 8) * 2;
        ldsm4(qa0, qa1, qa2, qa3, addr);
    }
    float nq0 = -qnb[n0 + w * 16 + (lane >> 2)];
    float nq1 = -qnb[n0 + w * 16 + (lane >> 2) + 8];

    uint32_t AKb0 = smem_u32(sK[0]) + (((grp >> 1) * 8 + lr) * 24 + (grp & 1) * 8) * 2;
    uint32_t AZb0 = smem_u32(sZ[0]) + ((grp >> 1) * 8 + lr) * 144 + ((grp & 1) * 8) * 2;
    const uint32_t KBUF = 64 * 24 * 2, ZBUF = 16 * 72 * 2;

    float O[2][4];
#pragma unroll
    for (int u = 0; u < 2; u++)
#pragma unroll
        for (int k = 0; k < 4; k++) O[u][k] = 0.f;
    float li0 = 0.f, li1 = 0.f;

    for (int t = 0; t < 36; t++) {
        int cur = t & 1;
        // issue next-tile loads first (overlap with compute)
        uint4 pK, pZ;
        float pN;
        if (t < 35) {
            int m0 = (t + 1) * 64;
            if (tid < 128) pK = qb4[(size_t)(m0 + krow) * 2 + khalf];
            else           pZ = *(const uint4*)(zb + (size_t)zc * Nn + m0 + zseg * 8);
            if (tid < 64)  pN = qnb[m0 + tid];
        }

        // K fragments
        uint32_t kf[8][2];
#pragma unroll
        for (int s = 0; s < 4; s++) {
            uint32_t r0, r1, r2, r3;
            ldsm4(r0, r1, r2, r3, AKb0 + cur * KBUF + s * 768);
            kf[2 * s][0] = r0; kf[2 * s][1] = r1;
            kf[2 * s + 1][0] = r2; kf[2 * s + 1][1] = r3;
        }

        // S mmas + softmax
        float p[8][4];
#pragma unroll
        for (int j = 0; j < 8; j++) {
            float2 kn2 = *(const float2*)&sKn[cur][8 * j + 2 * (lane & 3)];
            float d0, d1, d2, d3;
            mma16816(d0, d1, d2, d3, qa0, qa1, qa2, qa3, kf[j][0], kf[j][1],
                     nq0 - kn2.x, nq0 - kn2.y, nq1 - kn2.x, nq1 - kn2.y);
            p[j][0] = ex2(d0); p[j][1] = ex2(d1);
            p[j][2] = ex2(d2); p[j][3] = ex2(d3);
            li0 += p[j][0] + p[j][1];
            li1 += p[j][2] + p[j][3];
        }

        // PV mmas
#pragma unroll
        for (int s = 0; s < 4; s++) {
            uint32_t z0, z1, z2, z3;
            ldsm4(z0, z1, z2, z3, AZb0 + cur * ZBUF + s * 32);
            uint32_t a0 = cvt2(p[2 * s][0], p[2 * s][1]);
            uint32_t a1 = cvt2(p[2 * s][2], p[2 * s][3]);
            uint32_t a2 = cvt2(p[2 * s + 1][0], p[2 * s + 1][1]);
            uint32_t a3 = cvt2(p[2 * s + 1][2], p[2 * s + 1][3]);
            mma16816(O[0][0], O[0][1], O[0][2], O[0][3], a0, a1, a2, a3, z0, z1,
                     O[0][0], O[0][1], O[0][2], O[0][3]);
            mma16816(O[1][0], O[1][1], O[1][2], O[1][3], a0, a1, a2, a3, z2, z3,
                     O[1][0], O[1][1], O[1][2], O[1][3]);
        }

        // store next tile into other buffer
        if (t < 35) {
            int nxt = 1 - cur;
            if (tid < 128) *(uint4*)(sK[nxt] + krow * 24 + khalf * 8) = pK;
            else           *(uint4*)(sZ[nxt] + zc * 72 + zseg * 8) = pZ;
            if (tid < 64)  sKn[nxt][tid] = pN;
        }
        __syncthreads();
    }

    // quad-reduce li
    li0 += __shfl_xor_sync(0xffffffffu, li0, 1);
    li0 += __shfl_xor_sync(0xffffffffu, li0, 2);
    li1 += __shfl_xor_sync(0xffffffffu, li1, 1);
    li1 += __shfl_xor_sync(0xffffffffu, li1, 2);

    float i0 = 1.f / li0, i1 = 1.f / li1;
    int r0 = n0 + w * 16 + (lane >> 2);
    int r1 = r0 + 8;
    // permuted rows: row' = (n%36)*64 + n/36
    int pr0 = (r0 % 36) * 64 + r0 / 36;
    int pr1 = (r1 % 36) * 64 + r1 / 36;
    int cb = 2 * (lane & 3);
    float* ur0 = d_u + ((size_t)bh * Nn + pr0) * 16;
    float* ur1 = d_u + ((size_t)bh * Nn + pr1) * 16;
    *(float2*)(ur0 + cb)     = make_float2(O[0][0] * i0, O[0][1] * i0);
    *(float2*)(ur0 + cb + 8) = make_float2(O[1][0] * i0, O[1][1] * i0);
    *(float2*)(ur1 + cb)     = make_float2(O[0][2] * i1, O[0][3] * i1);
    *(float2*)(ur1 + cb + 8) = make_float2(O[1][2] * i1, O[1][3] * i1);
}

// ---------------- K_gv: fused g=U@R^T/4 and v=Wv@f_img+bv -------------------
// U permuted: U[36dd+a][c] lives at row a*64+dd -> contiguous per block
__global__ void __launch_bounds__(256) k_gv(const float* __restrict__ Wq,
                                            const float* __restrict__ Wv,
                                            const float* __restrict__ bv) {
    int bh = blockIdx.y;
    int h = bh & 3;
    int a = blockIdx.x;
    int tid = threadIdx.x;

    __shared__ float sT[64][17];   // T[dd][c]
    __shared__ float sWv[1024];
    __shared__ float sR[64][17];
    __shared__ float sM[16][17];

    {
        int dd = tid >> 2, cg = tid & 3;
        float4 v = *(const float4*)(d_u + ((size_t)bh * Nn + a * 64 + dd) * 16 + cg * 4);
        sT[dd][cg * 4 + 0] = v.x; sT[dd][cg * 4 + 1] = v.y;
        sT[dd][cg * 4 + 2] = v.z; sT[dd][cg * 4 + 3] = v.w;
        float4 rv = *(const float4*)(Wq + h * 1024 + dd * 16 + cg * 4);
        sR[dd][cg * 4 + 0] = rv.x; sR[dd][cg * 4 + 1] = rv.y;
        sR[dd][cg * 4 + 2] = rv.z; sR[dd][cg * 4 + 3] = rv.w;
    }
    for (int i = tid; i < 1024; i += 256) sWv[i] = Wv[h * 1024 + i];
    __syncthreads();

    {
        int k = tid >> 4, c = tid & 15;
        float acc = 0.f;
#pragma unroll
        for (int dd = 0; dd < 64; dd++) acc += sWv[k * 64 + dd] * sT[dd][c];
        sM[k][c] = acc;
    }
    __syncthreads();

    {
        int r = tid & 63, kg = tid >> 6;
        float vacc[4] = {0.f, 0.f, 0.f, 0.f};
#pragma unroll
        for (int c = 0; c < 16; c++) {
            float rc = sR[r][c];
            vacc[0] += sM[kg * 4 + 0][c] * rc;
            vacc[1] += sM[kg * 4 + 1][c] * rc;
            vacc[2] += sM[kg * 4 + 2][c] * rc;
            vacc[3] += sM[kg * 4 + 3][c] * rc;
        }
#pragma unroll
        for (int kk = 0; kk < 4; kk++) {
            int k = kg * 4 + kk;
            d_v[((size_t)bh * 16 + k) * Nn + a * 64 + r] = bv[h * 16 + k] + 0.25f * vacc[kk];
        }
    }
}

// ---------------- K_out: cat gather + Wo gemm + residual --------------------
__global__ void __launch_bounds__(256) k_out(const float* __restrict__ Wo,
                                             const float* __restrict__ bo,
                                             const float* __restrict__ gamma,
                                             const float* __restrict__ x,
                                             float* __restrict__ out) {
    int b = blockIdx.y;
    int n0 = blockIdx.x * 64;
    int a = n0 >> 6;
    int tid = threadIdx.x, ty = tid >> 4, tx = tid & 15;
    __shared__ __align__(16) float sC[64][68];
    __shared__ float sW[64][64];
    for (int i = tid; i < 4096; i += 256) {
        int dd = i >> 6, j = i & 63;
        int h = j >> 4, kk = j & 15;
        int vidx = (36 * dd + a) * 16 + kk;
        int vr = vidx / Nn;
        int vcol = vidx - vr * Nn;
        sC[dd][j] = d_v[((size_t)(b * Hh + h) * 16 + vr) * Nn + vcol];
    }
    for (int i = tid; i < 4096; i += 256) sW[i >> 6][i & 63] = Wo[i];
    __syncthreads();
    float acc[4][4];
#pragma unroll
    for (int i = 0; i < 4; i++)
#pragma unroll
        for (int c = 0; c < 4; c++) acc[i][c] = 0.f;
#pragma unroll 4
    for (int dd = 0; dd < 64; dd++) {
        float wv[4];
#pragma unroll
        for (int i = 0; i < 4; i++) wv[i] = sW[ty + 16 * i][dd];
        float4 cv = *(const float4*)(&sC[dd][tx * 4]);
#pragma unroll
        for (int i = 0; i < 4; i++) {
            acc[i][0] += wv[i] * cv.x;
            acc[i][1] += wv[i] * cv.y;
            acc[i][2] += wv[i] * cv.z;
            acc[i][3] += wv[i] * cv.w;
        }
    }
    float scale = gamma[0] / d_bound[0];
#pragma unroll
    for (int i = 0; i < 4; i++) {
        int o = ty + 16 * i;
        float bb = bo[o];
        size_t base = ((size_t)b * 64 + o) * Nn + n0 + tx * 4;
        float4 xin = *(const float4*)(&x[base]);
        float4 r;
        r.x = scale * (acc[i][0] + bb) + xin.x;
        r.y = scale * (acc[i][1] + bb) + xin.y;
        r.z = scale * (acc[i][2] + bb) + xin.z;
        r.w = scale * (acc[i][3] + bb) + xin.w;
        *(float4*)(&out[base]) = r;
    }
}

// ---------------- launch -----------------------------------------------------
extern "C" void kernel_launch(void* const* d_in, const int* in_sizes, int n_in,
                              void* d_out, int out_size) {
    const float* x     = (const float*)d_in[0];
    const float* Wq    = (const float*)d_in[1];
    const float* bq    = (const float*)d_in[2];
    const float* Wv    = (const float*)d_in[3];
    const float* bv    = (const float*)d_in[4];
    const float* Wo    = (const float*)d_in[5];
    const float* bo    = (const float*)d_in[6];
    const float* gamma = (const float*)d_in[7];
    float* out = (float*)d_out;

    k_qz   <<<dim3(Nn / 128, Bb, 9), 128>>>(x, Wq, bq, Wv, Wo);
    k_flash<<<dim3(Nn / 128, BHh), 256>>>();
    k_gv   <<<dim3(36, BHh), 256>>>(Wq, Wv, bv);
    k_out  <<<dim3(Nn / 64, Bb), 256>>>(Wo, bo, gamma, x, out);
}

// round 9
// speedup vs baseline: 2.8163x; 1.0276x over previous
#include <cuda_runtime.h>
#include <cuda_bf16.h>
#include <math.h>
#include <stdint.h>

#define Bb   4
#define Dd   64
#define Hh   4
#define DHd  16
#define Nn   2304
#define BHh  16   // B*heads

#define LOG2E 1.4426950408889634f
#define SC    0.8493218593f   // sqrt(0.5*log2e)

// ---------------- scratch (device globals) ----------------------------------
__device__ uint32_t d_qb[BHh * Nn * 8];          // q bf16x2: [bh][n][k/2], scaled by SC
__device__ float d_qn[BHh * Nn];                 // 0.25*log2e*||q||^2
__device__ __nv_bfloat16 d_zb[BHh * DHd * Nn];   // Z bf16: [bh][c][m]
__device__ float d_u[BHh * Nn * DHd];            // U permuted: row' = (n%36)*64 + n/36
__device__ float d_cat[Bb * Dd * Nn];            // cat_img[b][dd][n]
__device__ float d_bound[1];

__device__ __forceinline__ float ex2(float a) {
    float r;
    asm("ex2.approx.ftz.f32 %0, %1;" : "=f"(r) : "f"(a));
    return r;
}
__device__ __forceinline__ uint32_t cvt2(float lo, float hi) {
    uint32_t r;
    asm("cvt.rn.bf16x2.f32 %0, %1, %2;" : "=r"(r) : "f"(hi), "f"(lo));
    return r;
}
__device__ __forceinline__ uint32_t smem_u32(const void* p) {
    return (uint32_t)__cvta_generic_to_shared(p);
}
__device__ __forceinline__ void ldsm4(uint32_t& r0, uint32_t& r1, uint32_t& r2, uint32_t& r3,
                                      uint32_t addr) {
    asm volatile("ldmatrix.sync.aligned.m8n8.x4.shared.b16 {%0,%1,%2,%3}, [%4];"
                 : "=r"(r0), "=r"(r1), "=r"(r2), "=r"(r3) : "r"(addr));
}
__device__ __forceinline__ void mma16816(float& d0, float& d1, float& d2, float& d3,
                                         uint32_t a0, uint32_t a1, uint32_t a2, uint32_t a3,
                                         uint32_t b0, uint32_t b1,
                                         float c0, float c1, float c2, float c3) {
    asm volatile("mma.sync.aligned.m16n8k16.row.col.f32.bf16.bf16.f32 "
                 "{%0,%1,%2,%3},{%4,%5,%6,%7},{%8,%9},{%10,%11,%12,%13};"
                 : "=f"(d0), "=f"(d1), "=f"(d2), "=f"(d3)
                 : "r"(a0), "r"(a1), "r"(a2), "r"(a3), "r"(b0), "r"(b1),
                   "f"(c0), "f"(c1), "f"(c2), "f"(c3));
}

// ---------------- K_qz: z<4 -> q head z; z in[4,8) -> Z head z-4; z==8 -> bound
__global__ void __launch_bounds__(128) k_qz(const float* __restrict__ x,
                                            const float* __restrict__ Wq,
                                            const float* __restrict__ bq,
                                            const float* __restrict__ Wv,
                                            const float* __restrict__ Wo) {
    __shared__ float sW[DHd * Dd];
    int tid = threadIdx.x;
    int z = blockIdx.z;
    int b = blockIdx.y;

    if (z == 8) {
        if (blockIdx.x != 0 || blockIdx.y != 0) return;
        __shared__ float red[128];
        __shared__ float sq[Hh], sv[Hh];
        for (int h = 0; h < Hh; h++) {
            float a = 0.f;
            for (int i = tid; i < 1024; i += 128) { float w = Wq[h * 1024 + i]; a += w * w; }
            red[tid] = a; __syncthreads();
            for (int s = 64; s > 0; s >>= 1) { if (tid < s) red[tid] += red[tid + s]; __syncthreads(); }
            if (tid == 0) sq[h] = red[0];
            __syncthreads();
            a = 0.f;
            for (int i = tid; i < 1024; i += 128) { float w = Wv[h * 1024 + i]; a += w * w; }
            red[tid] = a; __syncthreads();
            for (int s = 64; s > 0; s >>= 1) { if (tid < s) red[tid] += red[tid + s]; __syncthreads(); }
            if (tid == 0) sv[h] = red[0];
            __syncthreads();
        }
        float a = 0.f;
        for (int i = tid; i < 4096; i += 128) { float w = Wo[i]; a += w * w; }
        red[tid] = a; __syncthreads();
        for (int s = 64; s > 0; s >>= 1) { if (tid < s) red[tid] += red[tid + s]; __syncthreads(); }
        if (tid == 0) {
            double zz = 2304.0 / 2.718281828459045;
            double w = log(zz) - log(log(zz));
            for (int it = 0; it < 30; it++) {
                double ew = exp(w);
                w = w - (w * ew - zz) / (ew * (w + 1.0));
            }
            float phi = (float)w;
            float term = sqrtf(sq[0] * sv[0] + sq[1] * sv[1] + sq[2] * sv[2] + sq[3] * sv[3]);
            d_bound[0] = sqrtf(2304.f / 64.f) * (4.f * phi + 1.f) * term * sqrtf(red[0]);
        }
        return;
    }

    if (z < 4) {
        int h = z;
        for (int i = tid; i < 1024; i += 128) sW[i] = Wq[h * 1024 + i];
        __syncthreads();
        int n = blockIdx.x * 128 + tid;
        int bh = b * Hh + h;
        const float* xb = x + b * Dd * Nn;
        float xv[Dd];
#pragma unroll
        for (int d = 0; d < Dd; d++) xv[d] = xb[d * Nn + n];
        float qv[DHd];
        float qn = 0.f;
#pragma unroll
        for (int k = 0; k < DHd; k++) {
            float acc = bq[h * DHd + k];
            const float* w = sW + k * Dd;
#pragma unroll
            for (int d = 0; d < Dd; d++) acc += w[d] * xv[d];
            qv[k] = acc;
            qn += acc * acc;
        }
        uint32_t pk[8];
#pragma unroll
        for (int i = 0; i < 8; i++) pk[i] = cvt2(SC * qv[2 * i], SC * qv[2 * i + 1]);
        uint4* dst = (uint4*)(d_qb + ((size_t)bh * Nn + n) * 8);
        dst[0] = make_uint4(pk[0], pk[1], pk[2], pk[3]);
        dst[1] = make_uint4(pk[4], pk[5], pk[6], pk[7]);
        d_qn[(size_t)bh * Nn + n] = qn * (0.25f * LOG2E);
    } else {
        int h = z - 4;
        for (int i = tid; i < 1024; i += 128) sW[i] = Wq[h * 1024 + i];
        __syncthreads();
        int m = blockIdx.x * 128 + tid;
        int bh = b * Hh + h;
        const float* xr = x + (size_t)b * Dd * Nn + (size_t)m * Dd;
        float acc[DHd];
#pragma unroll
        for (int c = 0; c < DHd; c++) acc[c] = 0.f;
#pragma unroll
        for (int dc = 0; dc < 16; dc++) {
            float4 v = *(const float4*)(xr + dc * 4);
            float xd[4] = {v.x, v.y, v.z, v.w};
#pragma unroll
            for (int q = 0; q < 4; q++) {
                const float4* rr = (const float4*)(sW + (dc * 4 + q) * 16);
#pragma unroll
                for (int cc = 0; cc < 4; cc++) {
                    float4 rv = rr[cc];
                    acc[cc * 4 + 0] += xd[q] * rv.x;
                    acc[cc * 4 + 1] += xd[q] * rv.y;
                    acc[cc * 4 + 2] += xd[q] * rv.z;
                    acc[cc * 4 + 3] += xd[q] * rv.w;
                }
            }
        }
#pragma unroll
        for (int c = 0; c < DHd; c++)
            d_zb[((size_t)bh * DHd + c) * Nn + m] = __float2bfloat16_rn(acc[c]);
    }
}

// ---------------- K1: flash, double-buffered, permuted U out -----------------
__global__ void __launch_bounds__(256) k_flash() {
    int bh = blockIdx.y;
    int n0 = blockIdx.x * 128;
    int tid = threadIdx.x;
    int w = tid >> 5, lane = tid & 31;
    int grp = lane >> 3, lr = lane & 7;

    __shared__ __align__(16) __nv_bfloat16 sQ[128 * 24];     // rows n, pitch 24
    __shared__ __align__(16) __nv_bfloat16 sK[2][64 * 24];   // rows m, pitch 24
    __shared__ __align__(16) __nv_bfloat16 sZ[2][16 * 72];   // rows c, pitch 72
    __shared__ float sKn[2][64];

    const uint4* qb4 = (const uint4*)d_qb + (size_t)bh * Nn * 2;
    const __nv_bfloat16* zb = d_zb + (size_t)bh * DHd * Nn;
    const float* qnb = d_qn + (size_t)bh * Nn;

    int krow = tid >> 1, khalf = tid & 1;
    int zc = (tid - 128) >> 3, zseg = (tid - 128) & 7;

    {
        int row = tid >> 1, half = tid & 1;
        *(uint4*)(sQ + row * 24 + half * 8) = qb4[(size_t)(n0 + row) * 2 + half];
    }
    if (tid < 128) *(uint4*)(sK[0] + krow * 24 + khalf * 8) = qb4[krow * 2 + khalf];
    else           *(uint4*)(sZ[0] + zc * 72 + zseg * 8) = *(const uint4*)(zb + (size_t)zc * Nn + zseg * 8);
    if (tid < 64)  sKn[0][tid] = qnb[tid];
    __syncthreads();

    uint32_t qa0, qa1, qa2, qa3;
    {
        uint32_t addr = smem_u32(sQ) + ((w * 16 + (grp & 1) * 8 + lr) * 24 + (grp >> 1) * 8) * 2;
        ldsm4(qa0, qa1, qa2, qa3, addr);
    }
    float nq0 = -qnb[n0 + w * 16 + (lane >> 2)];
    float nq1 = -qnb[n0 + w * 16 + (lane >> 2) + 8];

    uint32_t AKb0 = smem_u32(sK[0]) + (((grp >> 1) * 8 + lr) * 24 + (grp & 1) * 8) * 2;
    uint32_t AZb0 = smem_u32(sZ[0]) + ((grp >> 1) * 8 + lr) * 144 + ((grp & 1) * 8) * 2;
    const uint32_t KBUF = 64 * 24 * 2, ZBUF = 16 * 72 * 2;

    float O[2][4];
#pragma unroll
    for (int u = 0; u < 2; u++)
#pragma unroll
        for (int k = 0; k < 4; k++) O[u][k] = 0.f;
    float li0 = 0.f, li1 = 0.f;

    for (int t = 0; t < 36; t++) {
        int cur = t & 1;
        uint4 pK, pZ;
        float pN;
        if (t < 35) {
            int m0 = (t + 1) * 64;
            if (tid < 128) pK = qb4[(size_t)(m0 + krow) * 2 + khalf];
            else           pZ = *(const uint4*)(zb + (size_t)zc * Nn + m0 + zseg * 8);
            if (tid < 64)  pN = qnb[m0 + tid];
        }

        uint32_t kf[8][2];
#pragma unroll
        for (int s = 0; s < 4; s++) {
            uint32_t r0, r1, r2, r3;
            ldsm4(r0, r1, r2, r3, AKb0 + cur * KBUF + s * 768);
            kf[2 * s][0] = r0; kf[2 * s][1] = r1;
            kf[2 * s + 1][0] = r2; kf[2 * s + 1][1] = r3;
        }

        float p[8][4];
#pragma unroll
        for (int j = 0; j < 8; j++) {
            float2 kn2 = *(const float2*)&sKn[cur][8 * j + 2 * (lane & 3)];
            float d0, d1, d2, d3;
            mma16816(d0, d1, d2, d3, qa0, qa1, qa2, qa3, kf[j][0], kf[j][1],
                     nq0 - kn2.x, nq0 - kn2.y, nq1 - kn2.x, nq1 - kn2.y);
            p[j][0] = ex2(d0); p[j][1] = ex2(d1);
            p[j][2] = ex2(d2); p[j][3] = ex2(d3);
            li0 += p[j][0] + p[j][1];
            li1 += p[j][2] + p[j][3];
        }

#pragma unroll
        for (int s = 0; s < 4; s++) {
            uint32_t z0, z1, z2, z3;
            ldsm4(z0, z1, z2, z3, AZb0 + cur * ZBUF + s * 32);
            uint32_t a0 = cvt2(p[2 * s][0], p[2 * s][1]);
            uint32_t a1 = cvt2(p[2 * s][2], p[2 * s][3]);
            uint32_t a2 = cvt2(p[2 * s + 1][0], p[2 * s + 1][1]);
            uint32_t a3 = cvt2(p[2 * s + 1][2], p[2 * s + 1][3]);
            mma16816(O[0][0], O[0][1], O[0][2], O[0][3], a0, a1, a2, a3, z0, z1,
                     O[0][0], O[0][1], O[0][2], O[0][3]);
            mma16816(O[1][0], O[1][1], O[1][2], O[1][3], a0, a1, a2, a3, z2, z3,
                     O[1][0], O[1][1], O[1][2], O[1][3]);
        }

        if (t < 35) {
            int nxt = 1 - cur;
            if (tid < 128) *(uint4*)(sK[nxt] + krow * 24 + khalf * 8) = pK;
            else           *(uint4*)(sZ[nxt] + zc * 72 + zseg * 8) = pZ;
            if (tid < 64)  sKn[nxt][tid] = pN;
        }
        __syncthreads();
    }

    li0 += __shfl_xor_sync(0xffffffffu, li0, 1);
    li0 += __shfl_xor_sync(0xffffffffu, li0, 2);
    li1 += __shfl_xor_sync(0xffffffffu, li1, 1);
    li1 += __shfl_xor_sync(0xffffffffu, li1, 2);

    float i0 = 1.f / li0, i1 = 1.f / li1;
    int r0 = n0 + w * 16 + (lane >> 2);
    int r1 = r0 + 8;
    int pr0 = (r0 % 36) * 64 + r0 / 36;
    int pr1 = (r1 % 36) * 64 + r1 / 36;
    int cb = 2 * (lane & 3);
    float* ur0 = d_u + ((size_t)bh * Nn + pr0) * 16;
    float* ur1 = d_u + ((size_t)bh * Nn + pr1) * 16;
    *(float2*)(ur0 + cb)     = make_float2(O[0][0] * i0, O[0][1] * i0);
    *(float2*)(ur0 + cb + 8) = make_float2(O[1][0] * i0, O[1][1] * i0);
    *(float2*)(ur1 + cb)     = make_float2(O[0][2] * i1, O[0][3] * i1);
    *(float2*)(ur1 + cb + 8) = make_float2(O[1][2] * i1, O[1][3] * i1);
}

// ---------------- K_gv: fused g/v, writes directly into cat layout ----------
// value(k, vc=a*64+r) goes to cat[b][dd_c][n_c]:
//   s = k*144 + a*4 + (r>>4); dd_c = s/36; n_c = (s%36)*64 + h*16 + (r&15)
__global__ void __launch_bounds__(256) k_gv(const float* __restrict__ Wq,
                                            const float* __restrict__ Wv,
                                            const float* __restrict__ bv) {
    int bh = blockIdx.y;
    int h = bh & 3;
    int b = bh >> 2;
    int a = blockIdx.x;
    int tid = threadIdx.x;

    __shared__ float sT[64][17];   // T[dd][c] = U[a*64+dd][c] (permuted layout)
    __shared__ float sWv[1024];
    __shared__ float sR[64][17];
    __shared__ float sM[16][17];

    {
        int dd = tid >> 2, cg = tid & 3;
        float4 v = *(const float4*)(d_u + ((size_t)bh * Nn + a * 64 + dd) * 16 + cg * 4);
        sT[dd][cg * 4 + 0] = v.x; sT[dd][cg * 4 + 1] = v.y;
        sT[dd][cg * 4 + 2] = v.z; sT[dd][cg * 4 + 3] = v.w;
        float4 rv = *(const float4*)(Wq + h * 1024 + dd * 16 + cg * 4);
        sR[dd][cg * 4 + 0] = rv.x; sR[dd][cg * 4 + 1] = rv.y;
        sR[dd][cg * 4 + 2] = rv.z; sR[dd][cg * 4 + 3] = rv.w;
    }
    for (int i = tid; i < 1024; i += 256) sWv[i] = Wv[h * 1024 + i];
    __syncthreads();

    {
        int k = tid >> 4, c = tid & 15;
        float acc = 0.f;
#pragma unroll
        for (int dd = 0; dd < 64; dd++) acc += sWv[k * 64 + dd] * sT[dd][c];
        sM[k][c] = acc;
    }
    __syncthreads();

    {
        int r = tid & 63, kg = tid >> 6;
        float vacc[4] = {0.f, 0.f, 0.f, 0.f};
#pragma unroll
        for (int c = 0; c < 16; c++) {
            float rc = sR[r][c];
            vacc[0] += sM[kg * 4 + 0][c] * rc;
            vacc[1] += sM[kg * 4 + 1][c] * rc;
            vacc[2] += sM[kg * 4 + 2][c] * rc;
            vacc[3] += sM[kg * 4 + 3][c] * rc;
        }
        int rq = r >> 4, kkl = r & 15;
#pragma unroll
        for (int kk2 = 0; kk2 < 4; kk2++) {
            int k = kg * 4 + kk2;
            float val = bv[h * 16 + k] + 0.25f * vacc[kk2];
            int s = k * 144 + a * 4 + rq;
            int dd_c = s / 36;
            int a_c = s - dd_c * 36;
            int n_c = a_c * 64 + h * 16 + kkl;
            d_cat[((size_t)(b * 64 + dd_c)) * Nn + n_c] = val;
        }
    }
}

// ---------------- K_out: coalesced cat + Wo gemm + residual -----------------
__global__ void __launch_bounds__(256) k_out(const float* __restrict__ Wo,
                                             const float* __restrict__ bo,
                                             const float* __restrict__ gamma,
                                             const float* __restrict__ x,
                                             float* __restrict__ out) {
    int b = blockIdx.y;
    int n0 = blockIdx.x * 64;
    int tid = threadIdx.x, ty = tid >> 4, tx = tid & 15;
    __shared__ __align__(16) float sC[64][68];
    __shared__ float sW[64][64];
    for (int i = tid; i < 1024; i += 256) {
        int dd = i >> 4, jj = (i & 15) * 4;
        *(float4*)(&sC[dd][jj]) = *(const float4*)(d_cat + ((size_t)(b * 64 + dd)) * Nn + n0 + jj);
    }
    for (int i = tid; i < 4096; i += 256) sW[i >> 6][i & 63] = Wo[i];
    __syncthreads();
    float acc[4][4];
#pragma unroll
    for (int i = 0; i < 4; i++)
#pragma unroll
        for (int c = 0; c < 4; c++) acc[i][c] = 0.f;
#pragma unroll 4
    for (int dd = 0; dd < 64; dd++) {
        float wv[4];
#pragma unroll
        for (int i = 0; i < 4; i++) wv[i] = sW[ty + 16 * i][dd];
        float4 cv = *(const float4*)(&sC[dd][tx * 4]);
#pragma unroll
        for (int i = 0; i < 4; i++) {
            acc[i][0] += wv[i] * cv.x;
            acc[i][1] += wv[i] * cv.y;
            acc[i][2] += wv[i] * cv.z;
            acc[i][3] += wv[i] * cv.w;
        }
    }
    float scale = gamma[0] / d_bound[0];
#pragma unroll
    for (int i = 0; i < 4; i++) {
        int o = ty + 16 * i;
        float bb = bo[o];
        size_t base = ((size_t)b * 64 + o) * Nn + n0 + tx * 4;
        float4 xin = *(const float4*)(&x[base]);
        float4 r;
        r.x = scale * (acc[i][0] + bb) + xin.x;
        r.y = scale * (acc[i][1] + bb) + xin.y;
        r.z = scale * (acc[i][2] + bb) + xin.z;
        r.w = scale * (acc[i][3] + bb) + xin.w;
        *(float4*)(&out[base]) = r;
    }
}

// ---------------- launch -----------------------------------------------------
extern "C" void kernel_launch(void* const* d_in, const int* in_sizes, int n_in,
                              void* d_out, int out_size) {
    const float* x     = (const float*)d_in[0];
    const float* Wq    = (const float*)d_in[1];
    const float* bq    = (const float*)d_in[2];
    const float* Wv    = (const float*)d_in[3];
    const float* bv    = (const float*)d_in[4];
    const float* Wo    = (const float*)d_in[5];
    const float* bo    = (const float*)d_in[6];
    const float* gamma = (const float*)d_in[7];
    float* out = (float*)d_out;

    k_qz   <<<dim3(Nn / 128, Bb, 9), 128>>>(x, Wq, bq, Wv, Wo);
    k_flash<<<dim3(Nn / 128, BHh), 256>>>();
    k_gv   <<<dim3(36, BHh), 256>>>(Wq, Wv, bv);
    k_out  <<<dim3(Nn / 64, Bb), 256>>>(Wo, bo, gamma, x, out);
}

// round 10
// speedup vs baseline: 2.9301x; 1.0404x over previous
#include <cuda_runtime.h>
#include <cuda_bf16.h>
#include <math.h>
#include <stdint.h>

#define Bb   4
#define Dd   64
#define Hh   4
#define DHd  16
#define Nn   2304
#define BHh  16   // B*heads

#define LOG2E 1.4426950408889634f
#define SC    0.8493218593f   // sqrt(0.5*log2e)

// ---------------- scratch (device globals) ----------------------------------
__device__ uint32_t d_qb[BHh * Nn * 8];          // q bf16x2: [bh][n][k/2], scaled by SC
__device__ float d_qn[BHh * Nn];                 // 0.25*log2e*||q||^2
__device__ __nv_bfloat16 d_zb[BHh * DHd * Nn];   // Z bf16: [bh][c][m]
__device__ float d_u[BHh * Nn * DHd];            // U permuted: row' = (n%36)*64 + n/36
__device__ float d_cat[Bb * Dd * Nn];            // cat_img[b][dd][n]
__device__ float d_bound[1];

__device__ __forceinline__ float ex2(float a) {
    float r;
    asm("ex2.approx.ftz.f32 %0, %1;" : "=f"(r) : "f"(a));
    return r;
}
__device__ __forceinline__ uint32_t cvt2(float lo, float hi) {
    uint32_t r;
    asm("cvt.rn.bf16x2.f32 %0, %1, %2;" : "=r"(r) : "f"(hi), "f"(lo));
    return r;
}
__device__ __forceinline__ uint32_t smem_u32(const void* p) {
    return (uint32_t)__cvta_generic_to_shared(p);
}
__device__ __forceinline__ void ldsm4(uint32_t& r0, uint32_t& r1, uint32_t& r2, uint32_t& r3,
                                      uint32_t addr) {
    asm volatile("ldmatrix.sync.aligned.m8n8.x4.shared.b16 {%0,%1,%2,%3}, [%4];"
                 : "=r"(r0), "=r"(r1), "=r"(r2), "=r"(r3) : "r"(addr));
}
__device__ __forceinline__ void mma16816(float& d0, float& d1, float& d2, float& d3,
                                         uint32_t a0, uint32_t a1, uint32_t a2, uint32_t a3,
                                         uint32_t b0, uint32_t b1,
                                         float c0, float c1, float c2, float c3) {
    asm volatile("mma.sync.aligned.m16n8k16.row.col.f32.bf16.bf16.f32 "
                 "{%0,%1,%2,%3},{%4,%5,%6,%7},{%8,%9},{%10,%11,%12,%13};"
                 : "=f"(d0), "=f"(d1), "=f"(d2), "=f"(d3)
                 : "r"(a0), "r"(a1), "r"(a2), "r"(a3), "r"(b0), "r"(b1),
                   "f"(c0), "f"(c1), "f"(c2), "f"(c3));
}

// ---------------- K_qz: z<4 -> q head z; z in[4,8) -> Z head z-4; z==8 -> bound
__global__ void __launch_bounds__(128) k_qz(const float* __restrict__ x,
                                            const float* __restrict__ Wq,
                                            const float* __restrict__ bq,
                                            const float* __restrict__ Wv,
                                            const float* __restrict__ Wo) {
    __shared__ float sW[DHd * Dd];
    int tid = threadIdx.x;
    int z = blockIdx.z;
    int b = blockIdx.y;

    if (z == 8) {
        if (blockIdx.x != 0 || blockIdx.y != 0) return;
        __shared__ float red[128];
        __shared__ float sq[Hh], sv[Hh];
        for (int h = 0; h < Hh; h++) {
            float a = 0.f;
            for (int i = tid; i < 1024; i += 128) { float w = Wq[h * 1024 + i]; a += w * w; }
            red[tid] = a; __syncthreads();
            for (int s = 64; s > 0; s >>= 1) { if (tid < s) red[tid] += red[tid + s]; __syncthreads(); }
            if (tid == 0) sq[h] = red[0];
            __syncthreads();
            a = 0.f;
            for (int i = tid; i < 1024; i += 128) { float w = Wv[h * 1024 + i]; a += w * w; }
            red[tid] = a; __syncthreads();
            for (int s = 64; s > 0; s >>= 1) { if (tid < s) red[tid] += red[tid + s]; __syncthreads(); }
            if (tid == 0) sv[h] = red[0];
            __syncthreads();
        }
        float a = 0.f;
        for (int i = tid; i < 4096; i += 128) { float w = Wo[i]; a += w * w; }
        red[tid] = a; __syncthreads();
        for (int s = 64; s > 0; s >>= 1) { if (tid < s) red[tid] += red[tid + s]; __syncthreads(); }
        if (tid == 0) {
            double zz = 2304.0 / 2.718281828459045;
            double w = log(zz) - log(log(zz));
            for (int it = 0; it < 30; it++) {
                double ew = exp(w);
                w = w - (w * ew - zz) / (ew * (w + 1.0));
            }
            float phi = (float)w;
            float term = sqrtf(sq[0] * sv[0] + sq[1] * sv[1] + sq[2] * sv[2] + sq[3] * sv[3]);
            d_bound[0] = sqrtf(2304.f / 64.f) * (4.f * phi + 1.f) * term * sqrtf(red[0]);
        }
        return;
    }

    if (z < 4) {
        int h = z;
        for (int i = tid; i < 1024; i += 128) sW[i] = Wq[h * 1024 + i];
        __syncthreads();
        int n = blockIdx.x * 128 + tid;
        int bh = b * Hh + h;
        const float* xb = x + b * Dd * Nn;
        float xv[Dd];
#pragma unroll
        for (int d = 0; d < Dd; d++) xv[d] = xb[d * Nn + n];
        float qv[DHd];
        float qn = 0.f;
#pragma unroll
        for (int k = 0; k < DHd; k++) {
            float acc = bq[h * DHd + k];
            const float* w = sW + k * Dd;
#pragma unroll
            for (int d = 0; d < Dd; d++) acc += w[d] * xv[d];
            qv[k] = acc;
            qn += acc * acc;
        }
        uint32_t pk[8];
#pragma unroll
        for (int i = 0; i < 8; i++) pk[i] = cvt2(SC * qv[2 * i], SC * qv[2 * i + 1]);
        uint4* dst = (uint4*)(d_qb + ((size_t)bh * Nn + n) * 8);
        dst[0] = make_uint4(pk[0], pk[1], pk[2], pk[3]);
        dst[1] = make_uint4(pk[4], pk[5], pk[6], pk[7]);
        d_qn[(size_t)bh * Nn + n] = qn * (0.25f * LOG2E);
    } else {
        int h = z - 4;
        for (int i = tid; i < 1024; i += 128) sW[i] = Wq[h * 1024 + i];
        __syncthreads();
        int m = blockIdx.x * 128 + tid;
        int bh = b * Hh + h;
        const float* xr = x + (size_t)b * Dd * Nn + (size_t)m * Dd;
        float acc[DHd];
#pragma unroll
        for (int c = 0; c < DHd; c++) acc[c] = 0.f;
#pragma unroll
        for (int dc = 0; dc < 16; dc++) {
            float4 v = *(const float4*)(xr + dc * 4);
            float xd[4] = {v.x, v.y, v.z, v.w};
#pragma unroll
            for (int q = 0; q < 4; q++) {
                const float4* rr = (const float4*)(sW + (dc * 4 + q) * 16);
#pragma unroll
                for (int cc = 0; cc < 4; cc++) {
                    float4 rv = rr[cc];
                    acc[cc * 4 + 0] += xd[q] * rv.x;
                    acc[cc * 4 + 1] += xd[q] * rv.y;
                    acc[cc * 4 + 2] += xd[q] * rv.z;
                    acc[cc * 4 + 3] += xd[q] * rv.w;
                }
            }
        }
#pragma unroll
        for (int c = 0; c < DHd; c++)
            d_zb[((size_t)bh * DHd + c) * Nn + m] = __float2bfloat16_rn(acc[c]);
    }
}

// ---------------- K1: flash, double-buffered, permuted U out -----------------
__global__ void __launch_bounds__(256) k_flash() {
    int bh = blockIdx.y;
    int n0 = blockIdx.x * 128;
    int tid = threadIdx.x;
    int w = tid >> 5, lane = tid & 31;
    int grp = lane >> 3, lr = lane & 7;

    __shared__ __align__(16) __nv_bfloat16 sQ[128 * 24];     // rows n, pitch 24
    __shared__ __align__(16) __nv_bfloat16 sK[2][64 * 24];   // rows m, pitch 24
    __shared__ __align__(16) __nv_bfloat16 sZ[2][16 * 72];   // rows c, pitch 72
    __shared__ float sKn[2][64];

    const uint4* qb4 = (const uint4*)d_qb + (size_t)bh * Nn * 2;
    const __nv_bfloat16* zb = d_zb + (size_t)bh * DHd * Nn;
    const float* qnb = d_qn + (size_t)bh * Nn;

    int krow = tid >> 1, khalf = tid & 1;
    int zc = (tid - 128) >> 3, zseg = (tid - 128) & 7;

    {
        int row = tid >> 1, half = tid & 1;
        *(uint4*)(sQ + row * 24 + half * 8) = qb4[(size_t)(n0 + row) * 2 + half];
    }
    if (tid < 128) *(uint4*)(sK[0] + krow * 24 + khalf * 8) = qb4[krow * 2 + khalf];
    else           *(uint4*)(sZ[0] + zc * 72 + zseg * 8) = *(const uint4*)(zb + (size_t)zc * Nn + zseg * 8);
    if (tid < 64)  sKn[0][tid] = qnb[tid];
    __syncthreads();

    uint32_t qa0, qa1, qa2, qa3;
    {
        uint32_t addr = smem_u32(sQ) + ((w * 16 + (grp & 1) * 8 + lr) * 24 + (grp >> 1) * 8) * 2;
        ldsm4(qa0, qa1, qa2, qa3, addr);
    }
    float nq0 = -qnb[n0 + w * 16 + (lane >> 2)];
    float nq1 = -qnb[n0 + w * 16 + (lane >> 2) + 8];

    uint32_t AKb0 = smem_u32(sK[0]) + (((grp >> 1) * 8 + lr) * 24 + (grp & 1) * 8) * 2;
    uint32_t AZb0 = smem_u32(sZ[0]) + ((grp >> 1) * 8 + lr) * 144 + ((grp & 1) * 8) * 2;
    const uint32_t KBUF = 64 * 24 * 2, ZBUF = 16 * 72 * 2;

    float O[2][4];
#pragma unroll
    for (int u = 0; u < 2; u++)
#pragma unroll
        for (int k = 0; k < 4; k++) O[u][k] = 0.f;
    float li0 = 0.f, li1 = 0.f;

    for (int t = 0; t < 36; t++) {
        int cur = t & 1;
        uint4 pK, pZ;
        float pN;
        if (t < 35) {
            int m0 = (t + 1) * 64;
            if (tid < 128) pK = qb4[(size_t)(m0 + krow) * 2 + khalf];
            else           pZ = *(const uint4*)(zb + (size_t)zc * Nn + m0 + zseg * 8);
            if (tid < 64)  pN = qnb[m0 + tid];
        }

        uint32_t kf[8][2];
#pragma unroll
        for (int s = 0; s < 4; s++) {
            uint32_t r0, r1, r2, r3;
            ldsm4(r0, r1, r2, r3, AKb0 + cur * KBUF + s * 768);
            kf[2 * s][0] = r0; kf[2 * s][1] = r1;
            kf[2 * s + 1][0] = r2; kf[2 * s + 1][1] = r3;
        }

        float p[8][4];
#pragma unroll
        for (int j = 0; j < 8; j++) {
            float2 kn2 = *(const float2*)&sKn[cur][8 * j + 2 * (lane & 3)];
            float d0, d1, d2, d3;
            mma16816(d0, d1, d2, d3, qa0, qa1, qa2, qa3, kf[j][0], kf[j][1],
                     nq0 - kn2.x, nq0 - kn2.y, nq1 - kn2.x, nq1 - kn2.y);
            p[j][0] = ex2(d0); p[j][1] = ex2(d1);
            p[j][2] = ex2(d2); p[j][3] = ex2(d3);
            li0 += p[j][0] + p[j][1];
            li1 += p[j][2] + p[j][3];
        }

#pragma unroll
        for (int s = 0; s < 4; s++) {
            uint32_t z0, z1, z2, z3;
            ldsm4(z0, z1, z2, z3, AZb0 + cur * ZBUF + s * 32);
            uint32_t a0 = cvt2(p[2 * s][0], p[2 * s][1]);
            uint32_t a1 = cvt2(p[2 * s][2], p[2 * s][3]);
            uint32_t a2 = cvt2(p[2 * s + 1][0], p[2 * s + 1][1]);
            uint32_t a3 = cvt2(p[2 * s + 1][2], p[2 * s + 1][3]);
            mma16816(O[0][0], O[0][1], O[0][2], O[0][3], a0, a1, a2, a3, z0, z1,
                     O[0][0], O[0][1], O[0][2], O[0][3]);
            mma16816(O[1][0], O[1][1], O[1][2], O[1][3], a0, a1, a2, a3, z2, z3,
                     O[1][0], O[1][1], O[1][2], O[1][3]);
        }

        if (t < 35) {
            int nxt = 1 - cur;
            if (tid < 128) *(uint4*)(sK[nxt] + krow * 24 + khalf * 8) = pK;
            else           *(uint4*)(sZ[nxt] + zc * 72 + zseg * 8) = pZ;
            if (tid < 64)  sKn[nxt][tid] = pN;
        }
        __syncthreads();
    }

    li0 += __shfl_xor_sync(0xffffffffu, li0, 1);
    li0 += __shfl_xor_sync(0xffffffffu, li0, 2);
    li1 += __shfl_xor_sync(0xffffffffu, li1, 1);
    li1 += __shfl_xor_sync(0xffffffffu, li1, 2);

    float i0 = 1.f / li0, i1 = 1.f / li1;
    int r0 = n0 + w * 16 + (lane >> 2);
    int r1 = r0 + 8;
    int pr0 = (r0 % 36) * 64 + r0 / 36;
    int pr1 = (r1 % 36) * 64 + r1 / 36;
    int cb = 2 * (lane & 3);
    float* ur0 = d_u + ((size_t)bh * Nn + pr0) * 16;
    float* ur1 = d_u + ((size_t)bh * Nn + pr1) * 16;
    *(float2*)(ur0 + cb)     = make_float2(O[0][0] * i0, O[0][1] * i0);
    *(float2*)(ur0 + cb + 8) = make_float2(O[1][0] * i0, O[1][1] * i0);
    *(float2*)(ur1 + cb)     = make_float2(O[0][2] * i1, O[0][3] * i1);
    *(float2*)(ur1 + cb + 8) = make_float2(O[1][2] * i1, O[1][3] * i1);
}

// ---------------- K_gv: fused g/v, writes directly into cat layout ----------
__global__ void __launch_bounds__(256) k_gv(const float* __restrict__ Wq,
                                            const float* __restrict__ Wv,
                                            const float* __restrict__ bv) {
    int bh = blockIdx.y;
    int h = bh & 3;
    int b = bh >> 2;
    int a = blockIdx.x;
    int tid = threadIdx.x;

    __shared__ float sT[64][17];   // T[dd][c] = U[a*64+dd][c] (permuted layout)
    __shared__ float sWv[1024];
    __shared__ float sR[64][17];
    __shared__ float sM[16][17];

    {
        int dd = tid >> 2, cg = tid & 3;
        float4 v = *(const float4*)(d_u + ((size_t)bh * Nn + a * 64 + dd) * 16 + cg * 4);
        sT[dd][cg * 4 + 0] = v.x; sT[dd][cg * 4 + 1] = v.y;
        sT[dd][cg * 4 + 2] = v.z; sT[dd][cg * 4 + 3] = v.w;
        float4 rv = *(const float4*)(Wq + h * 1024 + dd * 16 + cg * 4);
        sR[dd][cg * 4 + 0] = rv.x; sR[dd][cg * 4 + 1] = rv.y;
        sR[dd][cg * 4 + 2] = rv.z; sR[dd][cg * 4 + 3] = rv.w;
    }
    for (int i = tid; i < 1024; i += 256) sWv[i] = Wv[h * 1024 + i];
    __syncthreads();

    {
        int k = tid >> 4, c = tid & 15;
        float acc = 0.f;
#pragma unroll
        for (int dd = 0; dd < 64; dd++) acc += sWv[k * 64 + dd] * sT[dd][c];
        sM[k][c] = acc;
    }
    __syncthreads();

    {
        int r = tid & 63, kg = tid >> 6;
        float vacc[4] = {0.f, 0.f, 0.f, 0.f};
#pragma unroll
        for (int c = 0; c < 16; c++) {
            float rc = sR[r][c];
            vacc[0] += sM[kg * 4 + 0][c] * rc;
            vacc[1] += sM[kg * 4 + 1][c] * rc;
            vacc[2] += sM[kg * 4 + 2][c] * rc;
            vacc[3] += sM[kg * 4 + 3][c] * rc;
        }
        int rq = r >> 4, kkl = r & 15;
#pragma unroll
        for (int kk2 = 0; kk2 < 4; kk2++) {
            int k = kg * 4 + kk2;
            float val = bv[h * 16 + k] + 0.25f * vacc[kk2];
            int s = k * 144 + a * 4 + rq;
            int dd_c = s / 36;
            int a_c = s - dd_c * 36;
            int n_c = a_c * 64 + h * 16 + kkl;
            d_cat[((size_t)(b * 64 + dd_c)) * Nn + n_c] = val;
        }
    }
}

// ---------------- K_out: 32(o) x 64(n) tiles, 288 blocks --------------------
__global__ void __launch_bounds__(256) k_out(const float* __restrict__ Wo,
                                             const float* __restrict__ bo,
                                             const float* __restrict__ gamma,
                                             const float* __restrict__ x,
                                             float* __restrict__ out) {
    int b = blockIdx.y;
    int n0 = blockIdx.x * 64;
    int ob = blockIdx.z * 32;
    int tid = threadIdx.x, ty = tid >> 4, tx = tid & 15;
    __shared__ __align__(16) float sC[64][68];
    __shared__ float sW[32][64];
    for (int i = tid; i < 1024; i += 256) {
        int dd = i >> 4, jj = (i & 15) * 4;
        *(float4*)(&sC[dd][jj]) = *(const float4*)(d_cat + ((size_t)(b * 64 + dd)) * Nn + n0 + jj);
    }
    for (int i = tid; i < 2048; i += 256)
        sW[i >> 6][i & 63] = Wo[(ob + (i >> 6)) * 64 + (i & 63)];
    __syncthreads();
    float acc[2][4];
#pragma unroll
    for (int i = 0; i < 2; i++)
#pragma unroll
        for (int c = 0; c < 4; c++) acc[i][c] = 0.f;
#pragma unroll 8
    for (int dd = 0; dd < 64; dd++) {
        float wv[2];
        wv[0] = sW[ty][dd];
        wv[1] = sW[ty + 16][dd];
        float4 cv = *(const float4*)(&sC[dd][tx * 4]);
#pragma unroll
        for (int i = 0; i < 2; i++) {
            acc[i][0] += wv[i] * cv.x;
            acc[i][1] += wv[i] * cv.y;
            acc[i][2] += wv[i] * cv.z;
            acc[i][3] += wv[i] * cv.w;
        }
    }
    float scale = gamma[0] / d_bound[0];
#pragma unroll
    for (int i = 0; i < 2; i++) {
        int o = ob + ty + 16 * i;
        float bb = bo[o];
        size_t base = ((size_t)b * 64 + o) * Nn + n0 + tx * 4;
        float4 xin = *(const float4*)(&x[base]);
        float4 r;
        r.x = scale * (acc[i][0] + bb) + xin.x;
        r.y = scale * (acc[i][1] + bb) + xin.y;
        r.z = scale * (acc[i][2] + bb) + xin.z;
        r.w = scale * (acc[i][3] + bb) + xin.w;
        *(float4*)(&out[base]) = r;
    }
}

// ---------------- launch -----------------------------------------------------
extern "C" void kernel_launch(void* const* d_in, const int* in_sizes, int n_in,
                              void* d_out, int out_size) {
    const float* x     = (const float*)d_in[0];
    const float* Wq    = (const float*)d_in[1];
    const float* bq    = (const float*)d_in[2];
    const float* Wv    = (const float*)d_in[3];
    const float* bv    = (const float*)d_in[4];
    const float* Wo    = (const float*)d_in[5];
    const float* bo    = (const float*)d_in[6];
    const float* gamma = (const float*)d_in[7];
    float* out = (float*)d_out;

    k_qz   <<<dim3(Nn / 128, Bb, 9), 128>>>(x, Wq, bq, Wv, Wo);
    k_flash<<<dim3(Nn / 128, BHh), 256>>>();
    k_gv   <<<dim3(36, BHh), 256>>>(Wq, Wv, bv);
    k_out  <<<dim3(Nn / 64, Bb, 2), 256>>>(Wo, bo, gamma, x, out);
}

// round 11
// speedup vs baseline: 2.9958x; 1.0224x over previous
#include <cuda_runtime.h>
#include <cuda_bf16.h>
#include <math.h>
#include <stdint.h>

#define Bb   4
#define Dd   64
#define Hh   4
#define DHd  16
#define Nn   2304
#define BHh  16   // B*heads

#define LOG2E 1.4426950408889634f
#define SC    0.8493218593f   // sqrt(0.5*log2e)

// ---------------- scratch (device globals) ----------------------------------
__device__ uint32_t d_qb[BHh * Nn * 8];          // q bf16x2: [bh][n][k/2], scaled by SC
__device__ float d_qn[BHh * Nn];                 // 0.25*log2e*||q||^2
__device__ __nv_bfloat16 d_zb[BHh * DHd * Nn];   // Z bf16: [bh][c][m]
__device__ float d_u[BHh * Nn * DHd];            // U permuted: row' = (n%36)*64 + n/36
__device__ float d_cat[Bb * Dd * Nn];            // cat_img[b][dd][n]
__device__ float d_bound[1];

__device__ __forceinline__ float ex2(float a) {
    float r;
    asm("ex2.approx.ftz.f32 %0, %1;" : "=f"(r) : "f"(a));
    return r;
}
__device__ __forceinline__ uint32_t cvt2(float lo, float hi) {
    uint32_t r;
    asm("cvt.rn.bf16x2.f32 %0, %1, %2;" : "=r"(r) : "f"(hi), "f"(lo));
    return r;
}
__device__ __forceinline__ uint32_t smem_u32(const void* p) {
    return (uint32_t)__cvta_generic_to_shared(p);
}
__device__ __forceinline__ void ldsm4(uint32_t& r0, uint32_t& r1, uint32_t& r2, uint32_t& r3,
                                      uint32_t addr) {
    asm volatile("ldmatrix.sync.aligned.m8n8.x4.shared.b16 {%0,%1,%2,%3}, [%4];"
                 : "=r"(r0), "=r"(r1), "=r"(r2), "=r"(r3) : "r"(addr));
}
__device__ __forceinline__ void mma16816(float& d0, float& d1, float& d2, float& d3,
                                         uint32_t a0, uint32_t a1, uint32_t a2, uint32_t a3,
                                         uint32_t b0, uint32_t b1,
                                         float c0, float c1, float c2, float c3) {
    asm volatile("mma.sync.aligned.m16n8k16.row.col.f32.bf16.bf16.f32 "
                 "{%0,%1,%2,%3},{%4,%5,%6,%7},{%8,%9},{%10,%11,%12,%13};"
                 : "=f"(d0), "=f"(d1), "=f"(d2), "=f"(d3)
                 : "r"(a0), "r"(a1), "r"(a2), "r"(a3), "r"(b0), "r"(b1),
                   "f"(c0), "f"(c1), "f"(c2), "f"(c3));
}

// ---------------- K_qz: z==0 -> q all heads; z==1 -> Z all heads; z==2 -> bound
__global__ void __launch_bounds__(128) k_qz(const float* __restrict__ x,
                                            const float* __restrict__ Wq,
                                            const float* __restrict__ bq,
                                            const float* __restrict__ Wv,
                                            const float* __restrict__ Wo) {
    __shared__ float sW[Hh * DHd * Dd];   // 4096 floats: all heads
    int tid = threadIdx.x;
    int z = blockIdx.z;
    int b = blockIdx.y;

    if (z == 2) {
        if (blockIdx.x != 0 || blockIdx.y != 0) return;
        __shared__ float red[128];
        __shared__ float sq[Hh], sv[Hh];
        for (int h = 0; h < Hh; h++) {
            float a = 0.f;
            for (int i = tid; i < 1024; i += 128) { float w = Wq[h * 1024 + i]; a += w * w; }
            red[tid] = a; __syncthreads();
            for (int s = 64; s > 0; s >>= 1) { if (tid < s) red[tid] += red[tid + s]; __syncthreads(); }
            if (tid == 0) sq[h] = red[0];
            __syncthreads();
            a = 0.f;
            for (int i = tid; i < 1024; i += 128) { float w = Wv[h * 1024 + i]; a += w * w; }
            red[tid] = a; __syncthreads();
            for (int s = 64; s > 0; s >>= 1) { if (tid < s) red[tid] += red[tid + s]; __syncthreads(); }
            if (tid == 0) sv[h] = red[0];
            __syncthreads();
        }
        float a = 0.f;
        for (int i = tid; i < 4096; i += 128) { float w = Wo[i]; a += w * w; }
        red[tid] = a; __syncthreads();
        for (int s = 64; s > 0; s >>= 1) { if (tid < s) red[tid] += red[tid + s]; __syncthreads(); }
        if (tid == 0) {
            double zz = 2304.0 / 2.718281828459045;
            double w = log(zz) - log(log(zz));
            for (int it = 0; it < 30; it++) {
                double ew = exp(w);
                w = w - (w * ew - zz) / (ew * (w + 1.0));
            }
            float phi = (float)w;
            float term = sqrtf(sq[0] * sv[0] + sq[1] * sv[1] + sq[2] * sv[2] + sq[3] * sv[3]);
            d_bound[0] = sqrtf(2304.f / 64.f) * (4.f * phi + 1.f) * term * sqrtf(red[0]);
        }
        return;
    }

    for (int i = tid; i < 4096; i += 128) sW[i] = Wq[i];
    __syncthreads();

    if (z == 0) {
        // q for all 4 heads; read x column once
        int n = blockIdx.x * 128 + tid;
        const float* xb = x + b * Dd * Nn;
        float xv[Dd];
#pragma unroll
        for (int d = 0; d < Dd; d++) xv[d] = xb[d * Nn + n];
        for (int h = 0; h < Hh; h++) {
            int bh = b * Hh + h;
            float qv[DHd];
            float qn = 0.f;
#pragma unroll
            for (int k = 0; k < DHd; k++) {
                float acc = bq[h * DHd + k];
                const float* w = sW + (h * DHd + k) * Dd;
#pragma unroll
                for (int d = 0; d < Dd; d++) acc += w[d] * xv[d];
                qv[k] = acc;
                qn += acc * acc;
            }
            uint32_t pk[8];
#pragma unroll
            for (int i = 0; i < 8; i++) pk[i] = cvt2(SC * qv[2 * i], SC * qv[2 * i + 1]);
            uint4* dst = (uint4*)(d_qb + ((size_t)bh * Nn + n) * 8);
            dst[0] = make_uint4(pk[0], pk[1], pk[2], pk[3]);
            dst[1] = make_uint4(pk[4], pk[5], pk[6], pk[7]);
            d_qn[(size_t)bh * Nn + n] = qn * (0.25f * LOG2E);
        }
    } else {
        // Z for all 4 heads; read x row once
        int m = blockIdx.x * 128 + tid;
        const float* xr = x + (size_t)b * Dd * Nn + (size_t)m * Dd;
        float xv[Dd];
#pragma unroll
        for (int dc = 0; dc < 16; dc++) {
            float4 v = *(const float4*)(xr + dc * 4);
            xv[dc * 4 + 0] = v.x; xv[dc * 4 + 1] = v.y;
            xv[dc * 4 + 2] = v.z; xv[dc * 4 + 3] = v.w;
        }
        for (int h = 0; h < Hh; h++) {
            int bh = b * Hh + h;
            float acc[DHd];
#pragma unroll
            for (int c = 0; c < DHd; c++) acc[c] = 0.f;
#pragma unroll
            for (int d = 0; d < Dd; d++) {
                float xd = xv[d];
                const float4* rr = (const float4*)(sW + h * 1024 + d * 16);
#pragma unroll
                for (int cc = 0; cc < 4; cc++) {
                    float4 rv = rr[cc];
                    acc[cc * 4 + 0] += xd * rv.x;
                    acc[cc * 4 + 1] += xd * rv.y;
                    acc[cc * 4 + 2] += xd * rv.z;
                    acc[cc * 4 + 3] += xd * rv.w;
                }
            }
#pragma unroll
            for (int c = 0; c < DHd; c++)
                d_zb[((size_t)bh * DHd + c) * Nn + m] = __float2bfloat16_rn(acc[c]);
        }
    }
}

// ---------------- K1: flash, double-buffered, permuted U out -----------------
__global__ void __launch_bounds__(256) k_flash() {
    int bh = blockIdx.y;
    int n0 = blockIdx.x * 128;
    int tid = threadIdx.x;
    int w = tid >> 5, lane = tid & 31;
    int grp = lane >> 3, lr = lane & 7;

    __shared__ __align__(16) __nv_bfloat16 sQ[128 * 24];     // rows n, pitch 24
    __shared__ __align__(16) __nv_bfloat16 sK[2][64 * 24];   // rows m, pitch 24
    __shared__ __align__(16) __nv_bfloat16 sZ[2][16 * 72];   // rows c, pitch 72
    __shared__ float sKn[2][64];

    const uint4* qb4 = (const uint4*)d_qb + (size_t)bh * Nn * 2;
    const __nv_bfloat16* zb = d_zb + (size_t)bh * DHd * Nn;
    const float* qnb = d_qn + (size_t)bh * Nn;

    int krow = tid >> 1, khalf = tid & 1;
    int zc = (tid - 128) >> 3, zseg = (tid - 128) & 7;

    {
        int row = tid >> 1, half = tid & 1;
        *(uint4*)(sQ + row * 24 + half * 8) = qb4[(size_t)(n0 + row) * 2 + half];
    }
    if (tid < 128) *(uint4*)(sK[0] + krow * 24 + khalf * 8) = qb4[krow * 2 + khalf];
    else           *(uint4*)(sZ[0] + zc * 72 + zseg * 8) = *(const uint4*)(zb + (size_t)zc * Nn + zseg * 8);
    if (tid < 64)  sKn[0][tid] = qnb[tid];
    __syncthreads();

    uint32_t qa0, qa1, qa2, qa3;
    {
        uint32_t addr = smem_u32(sQ) + ((w * 16 + (grp & 1) * 8 + lr) * 24 + (grp >> 1) * 8) * 2;
        ldsm4(qa0, qa1, qa2, qa3, addr);
    }
    float nq0 = -qnb[n0 + w * 16 + (lane >> 2)];
    float nq1 = -qnb[n0 + w * 16 + (lane >> 2) + 8];

    uint32_t AKb0 = smem_u32(sK[0]) + (((grp >> 1) * 8 + lr) * 24 + (grp & 1) * 8) * 2;
    uint32_t AZb0 = smem_u32(sZ[0]) + ((grp >> 1) * 8 + lr) * 144 + ((grp & 1) * 8) * 2;
    const uint32_t KBUF = 64 * 24 * 2, ZBUF = 16 * 72 * 2;

    float O[2][4];
#pragma unroll
    for (int u = 0; u < 2; u++)
#pragma unroll
        for (int k = 0; k < 4; k++) O[u][k] = 0.f;
    float li0 = 0.f, li1 = 0.f;

    for (int t = 0; t < 36; t++) {
        int cur = t & 1;
        uint4 pK, pZ;
        float pN;
        if (t < 35) {
            int m0 = (t + 1) * 64;
            if (tid < 128) pK = qb4[(size_t)(m0 + krow) * 2 + khalf];
            else           pZ = *(const uint4*)(zb + (size_t)zc * Nn + m0 + zseg * 8);
            if (tid < 64)  pN = qnb[m0 + tid];
        }

        uint32_t kf[8][2];
#pragma unroll
        for (int s = 0; s < 4; s++) {
            uint32_t r0, r1, r2, r3;
            ldsm4(r0, r1, r2, r3, AKb0 + cur * KBUF + s * 768);
            kf[2 * s][0] = r0; kf[2 * s][1] = r1;
            kf[2 * s + 1][0] = r2; kf[2 * s + 1][1] = r3;
        }

        float p[8][4];
#pragma unroll
        for (int j = 0; j < 8; j++) {
            float2 kn2 = *(const float2*)&sKn[cur][8 * j + 2 * (lane & 3)];
            float d0, d1, d2, d3;
            mma16816(d0, d1, d2, d3, qa0, qa1, qa2, qa3, kf[j][0], kf[j][1],
                     nq0 - kn2.x, nq0 - kn2.y, nq1 - kn2.x, nq1 - kn2.y);
            p[j][0] = ex2(d0); p[j][1] = ex2(d1);
            p[j][2] = ex2(d2); p[j][3] = ex2(d3);
            li0 += p[j][0] + p[j][1];
            li1 += p[j][2] + p[j][3];
        }

#pragma unroll
        for (int s = 0; s < 4; s++) {
            uint32_t z0, z1, z2, z3;
            ldsm4(z0, z1, z2, z3, AZb0 + cur * ZBUF + s * 32);
            uint32_t a0 = cvt2(p[2 * s][0], p[2 * s][1]);
            uint32_t a1 = cvt2(p[2 * s][2], p[2 * s][3]);
            uint32_t a2 = cvt2(p[2 * s + 1][0], p[2 * s + 1][1]);
            uint32_t a3 = cvt2(p[2 * s + 1][2], p[2 * s + 1][3]);
            mma16816(O[0][0], O[0][1], O[0][2], O[0][3], a0, a1, a2, a3, z0, z1,
                     O[0][0], O[0][1], O[0][2], O[0][3]);
            mma16816(O[1][0], O[1][1], O[1][2], O[1][3], a0, a1, a2, a3, z2, z3,
                     O[1][0], O[1][1], O[1][2], O[1][3]);
        }

        if (t < 35) {
            int nxt = 1 - cur;
            if (tid < 128) *(uint4*)(sK[nxt] + krow * 24 + khalf * 8) = pK;
            else           *(uint4*)(sZ[nxt] + zc * 72 + zseg * 8) = pZ;
            if (tid < 64)  sKn[nxt][tid] = pN;
        }
        __syncthreads();
    }

    li0 += __shfl_xor_sync(0xffffffffu, li0, 1);
    li0 += __shfl_xor_sync(0xffffffffu, li0, 2);
    li1 += __shfl_xor_sync(0xffffffffu, li1, 1);
    li1 += __shfl_xor_sync(0xffffffffu, li1, 2);

    float i0 = 1.f / li0, i1 = 1.f / li1;
    int r0 = n0 + w * 16 + (lane >> 2);
    int r1 = r0 + 8;
    int pr0 = (r0 % 36) * 64 + r0 / 36;
    int pr1 = (r1 % 36) * 64 + r1 / 36;
    int cb = 2 * (lane & 3);
    float* ur0 = d_u + ((size_t)bh * Nn + pr0) * 16;
    float* ur1 = d_u + ((size_t)bh * Nn + pr1) * 16;
    *(float2*)(ur0 + cb)     = make_float2(O[0][0] * i0, O[0][1] * i0);
    *(float2*)(ur0 + cb + 8) = make_float2(O[1][0] * i0, O[1][1] * i0);
    *(float2*)(ur1 + cb)     = make_float2(O[0][2] * i1, O[0][3] * i1);
    *(float2*)(ur1 + cb + 8) = make_float2(O[1][2] * i1, O[1][3] * i1);
}

// ---------------- K_gv: fused g/v, writes directly into cat layout ----------
__global__ void __launch_bounds__(256) k_gv(const float* __restrict__ Wq,
                                            const float* __restrict__ Wv,
                                            const float* __restrict__ bv) {
    int bh = blockIdx.y;
    int h = bh & 3;
    int b = bh >> 2;
    int a = blockIdx.x;
    int tid = threadIdx.x;

    __shared__ float sT[64][17];   // T[dd][c] = U[a*64+dd][c] (permuted layout)
    __shared__ float sWv[1024];
    __shared__ float sR[64][17];
    __shared__ float sM[16][17];

    {
        int dd = tid >> 2, cg = tid & 3;
        float4 v = *(const float4*)(d_u + ((size_t)bh * Nn + a * 64 + dd) * 16 + cg * 4);
        sT[dd][cg * 4 + 0] = v.x; sT[dd][cg * 4 + 1] = v.y;
        sT[dd][cg * 4 + 2] = v.z; sT[dd][cg * 4 + 3] = v.w;
        float4 rv = *(const float4*)(Wq + h * 1024 + dd * 16 + cg * 4);
        sR[dd][cg * 4 + 0] = rv.x; sR[dd][cg * 4 + 1] = rv.y;
        sR[dd][cg * 4 + 2] = rv.z; sR[dd][cg * 4 + 3] = rv.w;
    }
    for (int i = tid; i < 1024; i += 256) sWv[i] = Wv[h * 1024 + i];
    __syncthreads();

    {
        int k = tid >> 4, c = tid & 15;
        float acc = 0.f;
#pragma unroll
        for (int dd = 0; dd < 64; dd++) acc += sWv[k * 64 + dd] * sT[dd][c];
        sM[k][c] = acc;
    }
    __syncthreads();

    {
        int r = tid & 63, kg = tid >> 6;
        float vacc[4] = {0.f, 0.f, 0.f, 0.f};
#pragma unroll
        for (int c = 0; c < 16; c++) {
            float rc = sR[r][c];
            vacc[0] += sM[kg * 4 + 0][c] * rc;
            vacc[1] += sM[kg * 4 + 1][c] * rc;
            vacc[2] += sM[kg * 4 + 2][c] * rc;
            vacc[3] += sM[kg * 4 + 3][c] * rc;
        }
        int rq = r >> 4, kkl = r & 15;
#pragma unroll
        for (int kk2 = 0; kk2 < 4; kk2++) {
            int k = kg * 4 + kk2;
            float val = bv[h * 16 + k] + 0.25f * vacc[kk2];
            int s = k * 144 + a * 4 + rq;
            int dd_c = s / 36;
            int a_c = s - dd_c * 36;
            int n_c = a_c * 64 + h * 16 + kkl;
            d_cat[((size_t)(b * 64 + dd_c)) * Nn + n_c] = val;
        }
    }
}

// ---------------- K_out: 32(o) x 32(n) tiles, 576 blocks --------------------
__global__ void __launch_bounds__(256) k_out(const float* __restrict__ Wo,
                                             const float* __restrict__ bo,
                                             const float* __restrict__ gamma,
                                             const float* __restrict__ x,
                                             float* __restrict__ out) {
    int b = blockIdx.y;
    int n0 = blockIdx.x * 32;
    int ob = blockIdx.z * 32;
    int tid = threadIdx.x, ty = tid >> 3, tx = tid & 7;   // ty: 32 o-rows, tx: 8 n-quads
    __shared__ __align__(16) float sC[64][36];
    __shared__ float sW[32][64];
    for (int i = tid; i < 512; i += 256) {
        int dd = i >> 3, jj = (i & 7) * 4;
        *(float4*)(&sC[dd][jj]) = *(const float4*)(d_cat + ((size_t)(b * 64 + dd)) * Nn + n0 + jj);
    }
    for (int i = tid; i < 2048; i += 256)
        sW[i >> 6][i & 63] = Wo[(ob + (i >> 6)) * 64 + (i & 63)];
    __syncthreads();
    float a0 = 0.f, a1 = 0.f, a2 = 0.f, a3 = 0.f;
#pragma unroll 8
    for (int dd = 0; dd < 64; dd++) {
        float wv = sW[ty][dd];
        float4 cv = *(const float4*)(&sC[dd][tx * 4]);
        a0 += wv * cv.x;
        a1 += wv * cv.y;
        a2 += wv * cv.z;
        a3 += wv * cv.w;
    }
    float scale = gamma[0] / d_bound[0];
    int o = ob + ty;
    float bb = bo[o];
    size_t base = ((size_t)b * 64 + o) * Nn + n0 + tx * 4;
    float4 xin = *(const float4*)(&x[base]);
    float4 r;
    r.x = scale * (a0 + bb) + xin.x;
    r.y = scale * (a1 + bb) + xin.y;
    r.z = scale * (a2 + bb) + xin.z;
    r.w = scale * (a3 + bb) + xin.w;
    *(float4*)(&out[base]) = r;
}

// ---------------- launch -----------------------------------------------------
extern "C" void kernel_launch(void* const* d_in, const int* in_sizes, int n_in,
                              void* d_out, int out_size) {
    const float* x     = (const float*)d_in[0];
    const float* Wq    = (const float*)d_in[1];
    const float* bq    = (const float*)d_in[2];
    const float* Wv    = (const float*)d_in[3];
    const float* bv    = (const float*)d_in[4];
    const float* Wo    = (const float*)d_in[5];
    const float* bo    = (const float*)d_in[6];
    const float* gamma = (const float*)d_in[7];
    float* out = (float*)d_out;

    k_qz   <<<dim3(Nn / 128, Bb, 3), 128>>>(x, Wq, bq, Wv, Wo);
    k_flash<<<dim3(Nn / 128, BHh), 256>>>();
    k_gv   <<<dim3(36, BHh), 256>>>(Wq, Wv, bv);
    k_out  <<<dim3(Nn / 32, Bb, 2), 256>>>(Wo, bo, gamma, x, out);
}

// round 12
// speedup vs baseline: 3.0144x; 1.0062x over previous
#include <cuda_runtime.h>
#include <cuda_bf16.h>
#include <math.h>
#include <stdint.h>

#define Bb   4
#define Dd   64
#define Hh   4
#define DHd  16
#define Nn   2304
#define BHh  16   // B*heads

#define LOG2E 1.4426950408889634f
#define SC    0.8493218593f   // sqrt(0.5*log2e)

// ---------------- scratch (device globals) ----------------------------------
__device__ uint32_t d_qb[BHh * Nn * 8];          // q bf16x2: [bh][n][k/2], scaled by SC
__device__ float d_qn[BHh * Nn];                 // 0.25*log2e*||q||^2
__device__ __nv_bfloat16 d_zb[BHh * DHd * Nn];   // Z bf16: [bh][c][m]
__device__ float d_u[BHh * Nn * DHd];            // U permuted: row' = (n%36)*64 + n/36
__device__ float d_cat[Bb * Dd * Nn];            // cat_img[b][dd][n]
__device__ float d_bound[1];

__device__ __forceinline__ float ex2(float a) {
    float r;
    asm("ex2.approx.ftz.f32 %0, %1;" : "=f"(r) : "f"(a));
    return r;
}
__device__ __forceinline__ uint32_t cvt2(float lo, float hi) {
    uint32_t r;
    asm("cvt.rn.bf16x2.f32 %0, %1, %2;" : "=r"(r) : "f"(hi), "f"(lo));
    return r;
}
__device__ __forceinline__ uint32_t smem_u32(const void* p) {
    return (uint32_t)__cvta_generic_to_shared(p);
}
__device__ __forceinline__ void ldsm4(uint32_t& r0, uint32_t& r1, uint32_t& r2, uint32_t& r3,
                                      uint32_t addr) {
    asm volatile("ldmatrix.sync.aligned.m8n8.x4.shared.b16 {%0,%1,%2,%3}, [%4];"
                 : "=r"(r0), "=r"(r1), "=r"(r2), "=r"(r3) : "r"(addr));
}
__device__ __forceinline__ void mma16816(float& d0, float& d1, float& d2, float& d3,
                                         uint32_t a0, uint32_t a1, uint32_t a2, uint32_t a3,
                                         uint32_t b0, uint32_t b1,
                                         float c0, float c1, float c2, float c3) {
    asm volatile("mma.sync.aligned.m16n8k16.row.col.f32.bf16.bf16.f32 "
                 "{%0,%1,%2,%3},{%4,%5,%6,%7},{%8,%9},{%10,%11,%12,%13};"
                 : "=f"(d0), "=f"(d1), "=f"(d2), "=f"(d3)
                 : "r"(a0), "r"(a1), "r"(a2), "r"(a3), "r"(b0), "r"(b1),
                   "f"(c0), "f"(c1), "f"(c2), "f"(c3));
}

// ---------------- K_qz: z==0 -> q all heads; z==1 -> Z all heads; z==2 -> bound
__global__ void __launch_bounds__(128) k_qz(const float* __restrict__ x,
                                            const float* __restrict__ Wq,
                                            const float* __restrict__ bq,
                                            const float* __restrict__ Wv,
                                            const float* __restrict__ Wo) {
    __shared__ float sW[Hh * DHd * Dd];   // 4096 floats: all heads
    int tid = threadIdx.x;
    int z = blockIdx.z;
    int b = blockIdx.y;

    if (z == 2) {
        if (blockIdx.x != 0 || blockIdx.y != 0) return;
        __shared__ float red[128];
        __shared__ float sq[Hh], sv[Hh];
        for (int h = 0; h < Hh; h++) {
            float a = 0.f;
            for (int i = tid; i < 1024; i += 128) { float w = Wq[h * 1024 + i]; a += w * w; }
            red[tid] = a; __syncthreads();
            for (int s = 64; s > 0; s >>= 1) { if (tid < s) red[tid] += red[tid + s]; __syncthreads(); }
            if (tid == 0) sq[h] = red[0];
            __syncthreads();
            a = 0.f;
            for (int i = tid; i < 1024; i += 128) { float w = Wv[h * 1024 + i]; a += w * w; }
            red[tid] = a; __syncthreads();
            for (int s = 64; s > 0; s >>= 1) { if (tid < s) red[tid] += red[tid + s]; __syncthreads(); }
            if (tid == 0) sv[h] = red[0];
            __syncthreads();
        }
        float a = 0.f;
        for (int i = tid; i < 4096; i += 128) { float w = Wo[i]; a += w * w; }
        red[tid] = a; __syncthreads();
        for (int s = 64; s > 0; s >>= 1) { if (tid < s) red[tid] += red[tid + s]; __syncthreads(); }
        if (tid == 0) {
            double zz = 2304.0 / 2.718281828459045;
            double w = log(zz) - log(log(zz));
            for (int it = 0; it < 30; it++) {
                double ew = exp(w);
                w = w - (w * ew - zz) / (ew * (w + 1.0));
            }
            float phi = (float)w;
            float term = sqrtf(sq[0] * sv[0] + sq[1] * sv[1] + sq[2] * sv[2] + sq[3] * sv[3]);
            d_bound[0] = sqrtf(2304.f / 64.f) * (4.f * phi + 1.f) * term * sqrtf(red[0]);
        }
        return;
    }

    for (int i = tid; i < 4096; i += 128) sW[i] = Wq[i];
    __syncthreads();

    if (z == 0) {
        int n = blockIdx.x * 128 + tid;
        const float* xb = x + b * Dd * Nn;
        float xv[Dd];
#pragma unroll
        for (int d = 0; d < Dd; d++) xv[d] = xb[d * Nn + n];
        for (int h = 0; h < Hh; h++) {
            int bh = b * Hh + h;
            float qv[DHd];
            float qn = 0.f;
#pragma unroll
            for (int k = 0; k < DHd; k++) {
                float acc = bq[h * DHd + k];
                const float* w = sW + (h * DHd + k) * Dd;
#pragma unroll
                for (int d = 0; d < Dd; d++) acc += w[d] * xv[d];
                qv[k] = acc;
                qn += acc * acc;
            }
            uint32_t pk[8];
#pragma unroll
            for (int i = 0; i < 8; i++) pk[i] = cvt2(SC * qv[2 * i], SC * qv[2 * i + 1]);
            uint4* dst = (uint4*)(d_qb + ((size_t)bh * Nn + n) * 8);
            dst[0] = make_uint4(pk[0], pk[1], pk[2], pk[3]);
            dst[1] = make_uint4(pk[4], pk[5], pk[6], pk[7]);
            d_qn[(size_t)bh * Nn + n] = qn * (0.25f * LOG2E);
        }
    } else {
        int m = blockIdx.x * 128 + tid;
        const float* xr = x + (size_t)b * Dd * Nn + (size_t)m * Dd;
        float xv[Dd];
#pragma unroll
        for (int dc = 0; dc < 16; dc++) {
            float4 v = *(const float4*)(xr + dc * 4);
            xv[dc * 4 + 0] = v.x; xv[dc * 4 + 1] = v.y;
            xv[dc * 4 + 2] = v.z; xv[dc * 4 + 3] = v.w;
        }
        for (int h = 0; h < Hh; h++) {
            int bh = b * Hh + h;
            float acc[DHd];
#pragma unroll
            for (int c = 0; c < DHd; c++) acc[c] = 0.f;
#pragma unroll
            for (int d = 0; d < Dd; d++) {
                float xd = xv[d];
                const float4* rr = (const float4*)(sW + h * 1024 + d * 16);
#pragma unroll
                for (int cc = 0; cc < 4; cc++) {
                    float4 rv = rr[cc];
                    acc[cc * 4 + 0] += xd * rv.x;
                    acc[cc * 4 + 1] += xd * rv.y;
                    acc[cc * 4 + 2] += xd * rv.z;
                    acc[cc * 4 + 3] += xd * rv.w;
                }
            }
#pragma unroll
            for (int c = 0; c < DHd; c++)
                d_zb[((size_t)bh * DHd + c) * Nn + m] = __float2bfloat16_rn(acc[c]);
        }
    }
}

// ---------------- K1: flash, double-buffered, permuted U out -----------------
__global__ void __launch_bounds__(256) k_flash() {
    int bh = blockIdx.y;
    int n0 = blockIdx.x * 128;
    int tid = threadIdx.x;
    int w = tid >> 5, lane = tid & 31;
    int grp = lane >> 3, lr = lane & 7;

    __shared__ __align__(16) __nv_bfloat16 sQ[128 * 24];     // rows n, pitch 24
    __shared__ __align__(16) __nv_bfloat16 sK[2][64 * 24];   // rows m, pitch 24
    __shared__ __align__(16) __nv_bfloat16 sZ[2][16 * 72];   // rows c, pitch 72
    __shared__ float sKn[2][64];

    const uint4* qb4 = (const uint4*)d_qb + (size_t)bh * Nn * 2;
    const __nv_bfloat16* zb = d_zb + (size_t)bh * DHd * Nn;
    const float* qnb = d_qn + (size_t)bh * Nn;

    int krow = tid >> 1, khalf = tid & 1;
    int zc = (tid - 128) >> 3, zseg = (tid - 128) & 7;

    {
        int row = tid >> 1, half = tid & 1;
        *(uint4*)(sQ + row * 24 + half * 8) = qb4[(size_t)(n0 + row) * 2 + half];
    }
    if (tid < 128) *(uint4*)(sK[0] + krow * 24 + khalf * 8) = qb4[krow * 2 + khalf];
    else           *(uint4*)(sZ[0] + zc * 72 + zseg * 8) = *(const uint4*)(zb + (size_t)zc * Nn + zseg * 8);
    if (tid < 64)  sKn[0][tid] = qnb[tid];
    __syncthreads();

    uint32_t qa0, qa1, qa2, qa3;
    {
        uint32_t addr = smem_u32(sQ) + ((w * 16 + (grp & 1) * 8 + lr) * 24 + (grp >> 1) * 8) * 2;
        ldsm4(qa0, qa1, qa2, qa3, addr);
    }
    float nq0 = -qnb[n0 + w * 16 + (lane >> 2)];
    float nq1 = -qnb[n0 + w * 16 + (lane >> 2) + 8];

    uint32_t AKb0 = smem_u32(sK[0]) + (((grp >> 1) * 8 + lr) * 24 + (grp & 1) * 8) * 2;
    uint32_t AZb0 = smem_u32(sZ[0]) + ((grp >> 1) * 8 + lr) * 144 + ((grp & 1) * 8) * 2;
    const uint32_t KBUF = 64 * 24 * 2, ZBUF = 16 * 72 * 2;

    float O[2][4];
#pragma unroll
    for (int u = 0; u < 2; u++)
#pragma unroll
        for (int k = 0; k < 4; k++) O[u][k] = 0.f;
    float li0 = 0.f, li1 = 0.f;

    for (int t = 0; t < 36; t++) {
        int cur = t & 1;
        uint4 pK, pZ;
        float pN;
        if (t < 35) {
            int m0 = (t + 1) * 64;
            if (tid < 128) pK = qb4[(size_t)(m0 + krow) * 2 + khalf];
            else           pZ = *(const uint4*)(zb + (size_t)zc * Nn + m0 + zseg * 8);
            if (tid < 64)  pN = qnb[m0 + tid];
        }

        uint32_t kf[8][2];
#pragma unroll
        for (int s = 0; s < 4; s++) {
            uint32_t r0, r1, r2, r3;
            ldsm4(r0, r1, r2, r3, AKb0 + cur * KBUF + s * 768);
            kf[2 * s][0] = r0; kf[2 * s][1] = r1;
            kf[2 * s + 1][0] = r2; kf[2 * s + 1][1] = r3;
        }

        float p[8][4];
#pragma unroll
        for (int j = 0; j < 8; j++) {
            float2 kn2 = *(const float2*)&sKn[cur][8 * j + 2 * (lane & 3)];
            float d0, d1, d2, d3;
            mma16816(d0, d1, d2, d3, qa0, qa1, qa2, qa3, kf[j][0], kf[j][1],
                     nq0 - kn2.x, nq0 - kn2.y, nq1 - kn2.x, nq1 - kn2.y);
            p[j][0] = ex2(d0); p[j][1] = ex2(d1);
            p[j][2] = ex2(d2); p[j][3] = ex2(d3);
            li0 += p[j][0] + p[j][1];
            li1 += p[j][2] + p[j][3];
        }

#pragma unroll
        for (int s = 0; s < 4; s++) {
            uint32_t z0, z1, z2, z3;
            ldsm4(z0, z1, z2, z3, AZb0 + cur * ZBUF + s * 32);
            uint32_t a0 = cvt2(p[2 * s][0], p[2 * s][1]);
            uint32_t a1 = cvt2(p[2 * s][2], p[2 * s][3]);
            uint32_t a2 = cvt2(p[2 * s + 1][0], p[2 * s + 1][1]);
            uint32_t a3 = cvt2(p[2 * s + 1][2], p[2 * s + 1][3]);
            mma16816(O[0][0], O[0][1], O[0][2], O[0][3], a0, a1, a2, a3, z0, z1,
                     O[0][0], O[0][1], O[0][2], O[0][3]);
            mma16816(O[1][0], O[1][1], O[1][2], O[1][3], a0, a1, a2, a3, z2, z3,
                     O[1][0], O[1][1], O[1][2], O[1][3]);
        }

        if (t < 35) {
            int nxt = 1 - cur;
            if (tid < 128) *(uint4*)(sK[nxt] + krow * 24 + khalf * 8) = pK;
            else           *(uint4*)(sZ[nxt] + zc * 72 + zseg * 8) = pZ;
            if (tid < 64)  sKn[nxt][tid] = pN;
        }
        __syncthreads();
    }

    li0 += __shfl_xor_sync(0xffffffffu, li0, 1);
    li0 += __shfl_xor_sync(0xffffffffu, li0, 2);
    li1 += __shfl_xor_sync(0xffffffffu, li1, 1);
    li1 += __shfl_xor_sync(0xffffffffu, li1, 2);

    float i0 = 1.f / li0, i1 = 1.f / li1;
    int r0 = n0 + w * 16 + (lane >> 2);
    int r1 = r0 + 8;
    int pr0 = (r0 % 36) * 64 + r0 / 36;
    int pr1 = (r1 % 36) * 64 + r1 / 36;
    int cb = 2 * (lane & 3);
    float* ur0 = d_u + ((size_t)bh * Nn + pr0) * 16;
    float* ur1 = d_u + ((size_t)bh * Nn + pr1) * 16;
    *(float2*)(ur0 + cb)     = make_float2(O[0][0] * i0, O[0][1] * i0);
    *(float2*)(ur0 + cb + 8) = make_float2(O[1][0] * i0, O[1][1] * i0);
    *(float2*)(ur1 + cb)     = make_float2(O[0][2] * i1, O[0][3] * i1);
    *(float2*)(ur1 + cb + 8) = make_float2(O[1][2] * i1, O[1][3] * i1);
}

// ---------------- K_gv: fused g/v, writes directly into cat layout ----------
__global__ void __launch_bounds__(256) k_gv(const float* __restrict__ Wq,
                                            const float* __restrict__ Wv,
                                            const float* __restrict__ bv) {
    int bh = blockIdx.y;
    int h = bh & 3;
    int b = bh >> 2;
    int a = blockIdx.x;
    int tid = threadIdx.x;

    __shared__ float sT[64][17];   // T[dd][c] = U[a*64+dd][c] (permuted layout)
    __shared__ float sWv[1024];
    __shared__ float sR[64][17];
    __shared__ float sM[16][17];

    {
        int dd = tid >> 2, cg = tid & 3;
        float4 v = *(const float4*)(d_u + ((size_t)bh * Nn + a * 64 + dd) * 16 + cg * 4);
        sT[dd][cg * 4 + 0] = v.x; sT[dd][cg * 4 + 1] = v.y;
        sT[dd][cg * 4 + 2] = v.z; sT[dd][cg * 4 + 3] = v.w;
        float4 rv = *(const float4*)(Wq + h * 1024 + dd * 16 + cg * 4);
        sR[dd][cg * 4 + 0] = rv.x; sR[dd][cg * 4 + 1] = rv.y;
        sR[dd][cg * 4 + 2] = rv.z; sR[dd][cg * 4 + 3] = rv.w;
    }
    for (int i = tid; i < 1024; i += 256) sWv[i] = Wv[h * 1024 + i];
    __syncthreads();

    {
        int k = tid >> 4, c = tid & 15;
        float acc = 0.f;
#pragma unroll
        for (int dd = 0; dd < 64; dd++) acc += sWv[k * 64 + dd] * sT[dd][c];
        sM[k][c] = acc;
    }
    __syncthreads();

    {
        int r = tid & 63, kg = tid >> 6;
        float vacc[4] = {0.f, 0.f, 0.f, 0.f};
#pragma unroll
        for (int c = 0; c < 16; c++) {
            float rc = sR[r][c];
            vacc[0] += sM[kg * 4 + 0][c] * rc;
            vacc[1] += sM[kg * 4 + 1][c] * rc;
            vacc[2] += sM[kg * 4 + 2][c] * rc;
            vacc[3] += sM[kg * 4 + 3][c] * rc;
        }
        int rq = r >> 4, kkl = r & 15;
#pragma unroll
        for (int kk2 = 0; kk2 < 4; kk2++) {
            int k = kg * 4 + kk2;
            float val = bv[h * 16 + k] + 0.25f * vacc[kk2];
            int s = k * 144 + a * 4 + rq;
            int dd_c = s / 36;
            int a_c = s - dd_c * 36;
            int n_c = a_c * 64 + h * 16 + kkl;
            d_cat[((size_t)(b * 64 + dd_c)) * Nn + n_c] = val;
        }
    }
}

// ---------------- K_out: 64(n) x 16(o) tiles, 576 blocks, float4 loads ------
__global__ void __launch_bounds__(256) k_out(const float* __restrict__ Wo,
                                             const float* __restrict__ bo,
                                             const float* __restrict__ gamma,
                                             const float* __restrict__ x,
                                             float* __restrict__ out) {
    int b = blockIdx.y;
    int n0 = blockIdx.x * 64;
    int ob = blockIdx.z * 16;
    int tid = threadIdx.x, ty = tid >> 4, tx = tid & 15;  // ty: 16 o-rows, tx: 16 n-quads
    __shared__ __align__(16) float sC[64][68];
    __shared__ __align__(16) float sW[16][64];
    for (int i = tid; i < 1024; i += 256) {
        int dd = i >> 4, jj = (i & 15) * 4;
        *(float4*)(&sC[dd][jj]) = *(const float4*)(d_cat + ((size_t)(b * 64 + dd)) * Nn + n0 + jj);
    }
    {
        int row = tid >> 4, col = (tid & 15) * 4;   // 256 threads = 256 float4 exactly
        *(float4*)(&sW[row][col]) = *(const float4*)(Wo + (ob + row) * 64 + col);
    }
    __syncthreads();
    float a0 = 0.f, a1 = 0.f, a2 = 0.f, a3 = 0.f;
#pragma unroll 16
    for (int dd = 0; dd < 64; dd++) {
        float wv = sW[ty][dd];
        float4 cv = *(const float4*)(&sC[dd][tx * 4]);
        a0 += wv * cv.x;
        a1 += wv * cv.y;
        a2 += wv * cv.z;
        a3 += wv * cv.w;
    }
    float scale = gamma[0] / d_bound[0];
    int o = ob + ty;
    float bb = bo[o];
    size_t base = ((size_t)b * 64 + o) * Nn + n0 + tx * 4;
    float4 xin = *(const float4*)(&x[base]);
    float4 r;
    r.x = scale * (a0 + bb) + xin.x;
    r.y = scale * (a1 + bb) + xin.y;
    r.z = scale * (a2 + bb) + xin.z;
    r.w = scale * (a3 + bb) + xin.w;
    *(float4*)(&out[base]) = r;
}

// ---------------- launch -----------------------------------------------------
extern "C" void kernel_launch(void* const* d_in, const int* in_sizes, int n_in,
                              void* d_out, int out_size) {
    const float* x     = (const float*)d_in[0];
    const float* Wq    = (const float*)d_in[1];
    const float* bq    = (const float*)d_in[2];
    const float* Wv    = (const float*)d_in[3];
    const float* bv    = (const float*)d_in[4];
    const float* Wo    = (const float*)d_in[5];
    const float* bo    = (const float*)d_in[6];
    const float* gamma = (const float*)d_in[7];
    float* out = (float*)d_out;

    k_qz   <<<dim3(Nn / 128, Bb, 3), 128>>>(x, Wq, bq, Wv, Wo);
    k_flash<<<dim3(Nn / 128, BHh), 256>>>();
    k_gv   <<<dim3(36, BHh), 256>>>(Wq, Wv, bv);
    k_out  <<<dim3(Nn / 64, Bb, 4), 256>>>(Wo, bo, gamma, x, out);
}